// round 1
// baseline (speedup 1.0000x reference)
#include <cuda_runtime.h>
#include <cuda_bf16.h>
#include <math.h>

// ----- problem constants -----
#define BATCH   32
#define LD      512
#define LQ      32
#define EDIM    300
#define NF      4
#define DDIM    304           // E + NF
#define MWIN    16
#define ALPHA   0.9f
#define HID     1024          // 4*H
#define H2DIM   512           // 2*H
#define CIN     1212          // 3*D + E
#define RNUM    16            // R
#define PPL     9
#define NSAMP   144           // R*PPL
#define NEG_N   128
#define NLOC    145           // 1 pos + up to 144 distinct negative samples
#define NCOL    (BATCH*NLOC)  // 4640

// ----- scratch (device globals; no allocation allowed) -----
__device__ float g_F [(size_t)NCOL*CIN];
__device__ float g_H1[(size_t)NCOL*HID];
__device__ float g_H2[(size_t)NCOL*HID];
__device__ float g_H3[(size_t)NCOL*HID];
__device__ float g_H4[(size_t)NCOL*H2DIM];
__device__ float g_score[NCOL];
__device__ float g_qf[BATCH*EDIM];
__device__ int   g_used[NSAMP];
__device__ int   g_slot[NSAMP];
__device__ int   g_nused;

// ============================================================
// K0: dedup rand_idx -> used list + slot map (1 block)
// ============================================================
__global__ void k_prep(const int* __restrict__ rand_idx) {
    __shared__ int s_cnt[NSAMP];
    int tid = threadIdx.x;
    for (int i = tid; i < NSAMP; i += blockDim.x) s_cnt[i] = 0;
    __syncthreads();
    for (int n = tid; n < NEG_N; n += blockDim.x) {
        int s = rand_idx[n];
        s = min(max(s, 0), NSAMP - 1);   // jnp clamping gather semantics
        atomicAdd(&s_cnt[s], 1);
    }
    __syncthreads();
    if (tid == 0) {
        int u = 0;
        for (int s = 0; s < NSAMP; s++) {
            if (s_cnt[s] > 0) { g_used[u] = s; g_slot[s] = u + 1; u++; }
            else              { g_slot[s] = 0; }
        }
        g_nused = u;
    }
}

// ============================================================
// K1: query FOFE vector qf[b][e] = sum_t alpha^(LQ-1-t) emb[query[b,t],e]
// ============================================================
__global__ void k_qf(const int* __restrict__ query, const float* __restrict__ emb) {
    int b = blockIdx.x;
    int tid = threadIdx.x;
    __shared__ float qw[LQ];
    __shared__ int   tok[LQ];
    if (tid < LQ) {
        float w = 1.f;
        for (int k = 0; k < LQ - 1 - tid; k++) w *= ALPHA;
        qw[tid]  = w;
        tok[tid] = query[b * LQ + tid];
    }
    __syncthreads();
    for (int e = tid; e < EDIM; e += blockDim.x) {
        float acc = 0.f;
        #pragma unroll 4
        for (int t = 0; t < LQ; t++)
            acc += qw[t] * emb[(size_t)tok[t] * EDIM + e];
        g_qf[b * EDIM + e] = acc;
    }
}

// ============================================================
// K2: build feature matrix F[col][CIN]; col = b*NLOC + local
//   local 0       : [l_ctx | ans | r_ctx | qf]   (pos)
//   local 1+u     : [neg_l | neg_ans | neg_r | qf] for sample used[u]
// FOFE entries computed directly as <=17-term geometric sums.
// ============================================================
__device__ __forceinline__ float doc_x(const int* doc, const float* doc_f,
                                       const float* emb, int b, int ch, int t) {
    if (ch < EDIM) {
        int tokv = doc[b * LD + t];
        return emb[(size_t)tokv * EDIM + ch];
    }
    return doc_f[((size_t)(b * LD + t)) * NF + (ch - EDIM)];
}

__global__ void k_feat(const int* __restrict__ doc, const float* __restrict__ doc_f,
                       const float* __restrict__ emb,
                       const int* __restrict__ target_s, const int* __restrict__ target_e,
                       const int* __restrict__ rand_length, const int* __restrict__ rand_position) {
    int local = blockIdx.x;
    int b     = blockIdx.y;
    int nloc  = 1 + g_nused;
    if (local >= nloc) return;

    int base_l, pos_a, ka, base_r;
    if (local == 0) {
        int ts = target_s[b], te = target_e[b];
        base_l = max(ts - 1, 0);
        pos_a  = min(max(te, 0), LD - 1);
        ka     = te - ts;                 // span, 0..M-1
        base_r = min(te + 1, LD - 1);
    } else {
        int s  = g_used[local - 1];
        int i  = s / PPL, j = s % PPL;
        int rl = min(max(rand_length[i], 0), MWIN - 1);
        int p  = rand_position[i * PPL + j];
        p      = min(max(p, 0), LD - 1);
        pos_a  = p;
        ka     = rl;
        base_l = min(max(p - 1, 0), LD - 1);
        base_r = min(max(p + rl + 1, 0), LD - 1);
    }

    float* out = &g_F[(size_t)(b * NLOC + local) * CIN];
    for (int c = threadIdx.x; c < CIN; c += blockDim.x) {
        if (c < 3 * DDIM) {
            int seg = c / DDIM, ch = c % DDIM;
            float acc = 0.f, w = 1.f;
            if (seg == 0) {                 // left ctx: fwd[M-1] at base_l
                for (int k = 0; k <= MWIN - 1; k++) {
                    int t = base_l - k;
                    if (t >= 0) acc += w * doc_x(doc, doc_f, emb, b, ch, t);
                    w *= ALPHA;
                }
            } else if (seg == 1) {          // answer: fwd[ka] at pos_a
                for (int k = 0; k <= ka; k++) {
                    int t = pos_a - k;
                    if (t >= 0) acc += w * doc_x(doc, doc_f, emb, b, ch, t);
                    w *= ALPHA;
                }
            } else {                        // right ctx: inv[M-1] at base_r
                for (int k = 0; k <= MWIN - 1; k++) {
                    int t = base_r + k;
                    if (t < LD) acc += w * doc_x(doc, doc_f, emb, b, ch, t);
                    w *= ALPHA;
                }
            }
            out[c] = acc;
        } else {
            out[c] = g_qf[b * EDIM + (c - 3 * DDIM)];
        }
    }
}

// ============================================================
// K3: tiled NT-SGEMM with ReLU.
//   C[col][m] = relu( sum_k A[m][k] * Bm[col][k] )
//   A: [Mdim x K] row-major (weights), Bm: [NLOC per batch x K].
//   grid: (Mdim/128, ceil(NLOC/16), BATCH). Early-exit on unused column tiles.
// ============================================================
__global__ void k_gemm(const float* __restrict__ A, const float* __restrict__ Bm,
                       float* __restrict__ C, int Mdim, int K) {
    int nloc   = 1 + g_nused;
    int local0 = blockIdx.y * 16;
    if (local0 >= nloc) return;
    int b  = blockIdx.z;
    int m0 = blockIdx.x * 128;

    __shared__ float As[16][128];
    __shared__ float Bs[16][17];

    int tid = threadIdx.x;           // 256 threads
    int tx  = tid & 15;              // column within tile
    int ty  = tid >> 4;              // row group (8 rows each)
    float acc[8];
    #pragma unroll
    for (int i = 0; i < 8; i++) acc[i] = 0.f;

    const float* Bbase = Bm + (size_t)(b * NLOC) * K;
    int am    = tid >> 1;            // 0..127
    int kbase = (tid & 1) * 8;

    for (int k0 = 0; k0 < K; k0 += 16) {
        // A tile: 128 rows x 16 k (each thread: 8 consecutive k of one row)
        const float* Arow = A + (size_t)(m0 + am) * K + k0 + kbase;
        #pragma unroll
        for (int i = 0; i < 8; i++) {
            int kg = k0 + kbase + i;
            As[kbase + i][am] = (kg < K) ? Arow[i] : 0.f;
        }
        // B tile: 16 cols x 16 k (one element per thread)
        {
            int n  = tid & 15, kk = tid >> 4;
            int lc = local0 + n;
            int kg = k0 + kk;
            float v = 0.f;
            if (lc < nloc && kg < K) v = Bbase[(size_t)lc * K + kg];
            Bs[kk][n] = v;
        }
        __syncthreads();
        #pragma unroll
        for (int kk = 0; kk < 16; kk++) {
            float bv = Bs[kk][tx];
            const float* ar = &As[kk][ty * 8];
            #pragma unroll
            for (int i = 0; i < 8; i++) acc[i] += ar[i] * bv;
        }
        __syncthreads();
    }

    int local = local0 + tx;
    if (local < nloc) {
        float* Cc = C + (size_t)(b * NLOC + local) * Mdim + m0 + ty * 8;
        #pragma unroll
        for (int i = 0; i < 8; i++) {
            float v = acc[i];
            Cc[i] = v > 0.f ? v : 0.f;
        }
    }
}

// ============================================================
// K4: score[col] = sigmoid( W5 . H4[col] )
// ============================================================
__global__ void k_score(const float* __restrict__ W5) {
    int local = blockIdx.x, b = blockIdx.y;
    if (local >= 1 + g_nused) return;
    const float* h = &g_H4[(size_t)(b * NLOC + local) * H2DIM];
    int tid = threadIdx.x;   // 128
    float acc = 0.f;
    for (int i = tid; i < H2DIM; i += 128) acc += W5[i] * h[i];
    #pragma unroll
    for (int o = 16; o; o >>= 1) acc += __shfl_down_sync(0xffffffffu, acc, o);
    __shared__ float sh[4];
    if ((tid & 31) == 0) sh[tid >> 5] = acc;
    __syncthreads();
    if (tid == 0) {
        float s = sh[0] + sh[1] + sh[2] + sh[3];
        g_score[b * NLOC + local] = 1.f / (1.f + expf(-s));
    }
}

// ============================================================
// K5: loss = sum_b [ 128*(pos-1)^2 + sum_n (score[slot(rand_idx[n])])^2 ]
// (permutation-invariant; perm_idx drops out exactly)
// ============================================================
__global__ void k_loss(const int* __restrict__ rand_idx, float* __restrict__ out) {
    int tid = threadIdx.x;   // 256
    float acc = 0.f;
    for (int idx = tid; idx < BATCH * NEG_N; idx += 256) {
        int b = idx >> 7, n = idx & 127;
        int s = rand_idx[n];
        s = min(max(s, 0), NSAMP - 1);
        int u = g_slot[s];                    // >=1 by construction
        float v = g_score[b * NLOC + u];
        acc += v * v;
    }
    if (tid < BATCH) {
        float v = g_score[tid * NLOC] - 1.f;
        acc += 128.f * v * v;
    }
    __shared__ float sh[256];
    sh[tid] = acc;
    __syncthreads();
    for (int o = 128; o; o >>= 1) {
        if (tid < o) sh[tid] += sh[tid + o];
        __syncthreads();
    }
    if (tid == 0) out[0] = sh[0];
}

// ============================================================
// launch
// ============================================================
extern "C" void kernel_launch(void* const* d_in, const int* in_sizes, int n_in,
                              void* d_out, int out_size) {
    const int*   doc       = (const int*)  d_in[0];
    const float* doc_f     = (const float*)d_in[1];
    const int*   query     = (const int*)  d_in[2];
    const int*   target_s  = (const int*)  d_in[3];
    const int*   target_e  = (const int*)  d_in[4];
    // d_in[5] doc_mask, d_in[6] query_mask: unused by reference
    const float* emb       = (const float*)d_in[7];
    const float* W1        = (const float*)d_in[8];
    const float* W2        = (const float*)d_in[9];
    const float* W3        = (const float*)d_in[10];
    const float* W4        = (const float*)d_in[11];
    const float* W5        = (const float*)d_in[12];
    const int*   rand_len  = (const int*)  d_in[13];
    const int*   rand_pos  = (const int*)  d_in[14];
    const int*   rand_idx  = (const int*)  d_in[15];
    // d_in[16] perm_idx: permutation-invariant loss -> unused
    float* out = (float*)d_out;

    float *F, *H1, *H2, *H3, *H4;
    cudaGetSymbolAddress((void**)&F,  g_F);
    cudaGetSymbolAddress((void**)&H1, g_H1);
    cudaGetSymbolAddress((void**)&H2, g_H2);
    cudaGetSymbolAddress((void**)&H3, g_H3);
    cudaGetSymbolAddress((void**)&H4, g_H4);

    k_prep<<<1, 256>>>(rand_idx);
    k_qf  <<<BATCH, 128>>>(query, emb);
    {
        dim3 g(NLOC, BATCH);
        k_feat<<<g, 256>>>(doc, doc_f, emb, target_s, target_e, rand_len, rand_pos);
    }
    {
        dim3 g1(HID / 128,   (NLOC + 15) / 16, BATCH);
        dim3 g4(H2DIM / 128, (NLOC + 15) / 16, BATCH);
        k_gemm<<<g1, 256>>>(W1, F,  H1, HID,   CIN);
        k_gemm<<<g1, 256>>>(W2, H1, H2, HID,   HID);
        k_gemm<<<g1, 256>>>(W3, H2, H3, HID,   HID);
        k_gemm<<<g4, 256>>>(W4, H3, H4, H2DIM, HID);
    }
    {
        dim3 g(NLOC, BATCH);
        k_score<<<g, 128>>>(W5);
    }
    k_loss<<<1, 256>>>(rand_idx, out);
}

// round 2
// speedup vs baseline: 1.8536x; 1.8536x over previous
#include <cuda_runtime.h>
#include <cuda_bf16.h>
#include <math.h>

// ----- problem constants -----
#define BATCH   32
#define LD      512
#define LQ      32
#define EDIM    300
#define NF      4
#define DDIM    304           // E + NF
#define MWIN    16
#define ALPHA   0.9f
#define HID     1024          // 4*H
#define H2DIM   512           // 2*H
#define CIN     1212          // 3*D + E
#define PPL     9
#define NSAMP   144           // R*PPL
#define NEG_N   128
#define NLOC    145           // 1 pos + up to 144 distinct negatives (worst case)
#define NCOL    (BATCH*NLOC)  // 4640 worst case
#define NTILE   64
#define NTILES  ((NCOL + NTILE - 1) / NTILE)   // 73

// ----- scratch (device globals; no allocation allowed) -----
__device__ float g_F [(size_t)NCOL*CIN];
__device__ float g_H1[(size_t)NCOL*HID];
__device__ float g_H2[(size_t)NCOL*HID];
__device__ float g_H3[(size_t)NCOL*HID];
__device__ float g_H4[(size_t)NCOL*H2DIM];
__device__ float g_score[NCOL];
__device__ float g_qf[BATCH*EDIM];
__device__ int   g_used[NSAMP];
__device__ int   g_slot[NSAMP];
__device__ int   g_nused;

// ============================================================
// K0: dedup rand_idx -> used list + slot map (1 block)
// ============================================================
__global__ void k_prep(const int* __restrict__ rand_idx) {
    __shared__ int s_cnt[NSAMP];
    int tid = threadIdx.x;
    for (int i = tid; i < NSAMP; i += blockDim.x) s_cnt[i] = 0;
    __syncthreads();
    for (int n = tid; n < NEG_N; n += blockDim.x) {
        int s = rand_idx[n];
        s = min(max(s, 0), NSAMP - 1);   // jnp clamping gather semantics
        atomicAdd(&s_cnt[s], 1);
    }
    __syncthreads();
    if (tid == 0) {
        int u = 0;
        for (int s = 0; s < NSAMP; s++) {
            if (s_cnt[s] > 0) { g_used[u] = s; g_slot[s] = u + 1; u++; }
            else              { g_slot[s] = 0; }
        }
        g_nused = u;
    }
}

// ============================================================
// K1: query FOFE vector qf[b][e] = sum_t alpha^(LQ-1-t) emb[query[b,t],e]
// ============================================================
__global__ void k_qf(const int* __restrict__ query, const float* __restrict__ emb) {
    int b = blockIdx.x;
    int tid = threadIdx.x;
    __shared__ float qw[LQ];
    __shared__ int   tok[LQ];
    if (tid < LQ) {
        float w = 1.f;
        for (int k = 0; k < LQ - 1 - tid; k++) w *= ALPHA;
        qw[tid]  = w;
        tok[tid] = query[b * LQ + tid];
    }
    __syncthreads();
    for (int e = tid; e < EDIM; e += blockDim.x) {
        float acc = 0.f;
        #pragma unroll 4
        for (int t = 0; t < LQ; t++)
            acc += qw[t] * emb[(size_t)tok[t] * EDIM + e];
        g_qf[b * EDIM + e] = acc;
    }
}

// ============================================================
// K2: build COMPACT feature matrix F[col][CIN]; col = b*nloc + local
// ============================================================
__device__ __forceinline__ float doc_x(const int* doc, const float* doc_f,
                                       const float* emb, int b, int ch, int t) {
    if (ch < EDIM) {
        int tokv = doc[b * LD + t];
        return emb[(size_t)tokv * EDIM + ch];
    }
    return doc_f[((size_t)(b * LD + t)) * NF + (ch - EDIM)];
}

__global__ void k_feat(const int* __restrict__ doc, const float* __restrict__ doc_f,
                       const float* __restrict__ emb,
                       const int* __restrict__ target_s, const int* __restrict__ target_e,
                       const int* __restrict__ rand_length, const int* __restrict__ rand_position) {
    int local = blockIdx.x;
    int b     = blockIdx.y;
    int nloc  = 1 + g_nused;
    if (local >= nloc) return;

    int base_l, pos_a, ka, base_r;
    if (local == 0) {
        int ts = target_s[b], te = target_e[b];
        base_l = max(ts - 1, 0);
        pos_a  = min(max(te, 0), LD - 1);
        ka     = te - ts;                 // span, 0..M-1
        base_r = min(te + 1, LD - 1);
    } else {
        int s  = g_used[local - 1];
        int i  = s / PPL, j = s % PPL;
        int rl = min(max(rand_length[i], 0), MWIN - 1);
        int p  = rand_position[i * PPL + j];
        p      = min(max(p, 0), LD - 1);
        pos_a  = p;
        ka     = rl;
        base_l = min(max(p - 1, 0), LD - 1);
        base_r = min(max(p + rl + 1, 0), LD - 1);
    }

    float* out = &g_F[(size_t)(b * nloc + local) * CIN];
    for (int c = threadIdx.x; c < CIN; c += blockDim.x) {
        if (c < 3 * DDIM) {
            int seg = c / DDIM, ch = c % DDIM;
            float acc = 0.f, w = 1.f;
            if (seg == 0) {                 // left ctx: fwd[M-1] at base_l
                for (int k = 0; k <= MWIN - 1; k++) {
                    int t = base_l - k;
                    if (t >= 0) acc += w * doc_x(doc, doc_f, emb, b, ch, t);
                    w *= ALPHA;
                }
            } else if (seg == 1) {          // answer: fwd[ka] at pos_a
                for (int k = 0; k <= ka; k++) {
                    int t = pos_a - k;
                    if (t >= 0) acc += w * doc_x(doc, doc_f, emb, b, ch, t);
                    w *= ALPHA;
                }
            } else {                        // right ctx: inv[M-1] at base_r
                for (int k = 0; k <= MWIN - 1; k++) {
                    int t = base_r + k;
                    if (t < LD) acc += w * doc_x(doc, doc_f, emb, b, ch, t);
                    w *= ALPHA;
                }
            }
            out[c] = acc;
        } else {
            out[c] = g_qf[b * EDIM + (c - 3 * DDIM)];
        }
    }
}

// ============================================================
// K3: fused NT-SGEMM + ReLU over ALL compacted columns.
//   C[n][m] = relu( sum_k A[m][k] * Bm[n][k] ),  n = compact column id
//   Tile 128(M) x 64(N) x 16(K), 256 threads, 8x4 outputs/thread.
// ============================================================
__global__ __launch_bounds__(256, 3)
void k_gemm(const float* __restrict__ A, const float* __restrict__ Bm,
            float* __restrict__ C, int Mdim, int K) {
    int ncols = BATCH * (1 + g_nused);
    int n0 = blockIdx.y * NTILE;
    if (n0 >= ncols) return;
    int m0 = blockIdx.x * 128;

    __shared__ float As[16][132];
    __shared__ float Bs[16][68];

    int tid = threadIdx.x;
    int tx  = tid & 15;              // M sub-tile: 8 rows at tx*8
    int ty  = tid >> 4;              // N sub-tile: 4 cols at ty*4

    float acc[8][4];
    #pragma unroll
    for (int i = 0; i < 8; i++)
        #pragma unroll
        for (int j = 0; j < 4; j++) acc[i][j] = 0.f;

    // A-load mapping: row am = tid>>1, k offset ak = (tid&1)*8  (2x float4)
    int am = tid >> 1;
    int ak = (tid & 1) * 8;
    // B-load mapping: row bn = tid>>2, k offset bk = (tid&3)*4  (1x float4)
    int bn = tid >> 2;
    int bk = (tid & 3) * 4;

    const float* Arow = A  + (size_t)(m0 + am) * K + ak;
    const float* Brow = Bm + (size_t)(n0 + bn) * K + bk;
    bool bvalid = (n0 + bn) < ncols;

    for (int k0 = 0; k0 < K; k0 += 16) {
        // ---- A tile: 128 x 16 ----
        if (k0 + 16 <= K) {
            float4 a0 = *(const float4*)(Arow + k0);
            float4 a1 = *(const float4*)(Arow + k0 + 4);
            As[ak+0][am] = a0.x; As[ak+1][am] = a0.y; As[ak+2][am] = a0.z; As[ak+3][am] = a0.w;
            As[ak+4][am] = a1.x; As[ak+5][am] = a1.y; As[ak+6][am] = a1.z; As[ak+7][am] = a1.w;
        } else {
            #pragma unroll
            for (int i = 0; i < 8; i++) {
                int kg = k0 + ak + i;
                As[ak + i][am] = (kg < K) ? Arow[k0 + i] : 0.f;
            }
        }
        // ---- B tile: 64 x 16 ----
        {
            float4 bv = make_float4(0.f, 0.f, 0.f, 0.f);
            if (bvalid && (k0 + bk + 4 <= K)) {
                bv = *(const float4*)(Brow + k0);
            } else if (bvalid) {
                float t[4] = {0.f, 0.f, 0.f, 0.f};
                #pragma unroll
                for (int i = 0; i < 4; i++) {
                    int kg = k0 + bk + i;
                    if (kg < K) t[i] = Brow[k0 + i];
                }
                bv = make_float4(t[0], t[1], t[2], t[3]);
            }
            Bs[bk+0][bn] = bv.x; Bs[bk+1][bn] = bv.y; Bs[bk+2][bn] = bv.z; Bs[bk+3][bn] = bv.w;
        }
        __syncthreads();

        #pragma unroll
        for (int kk = 0; kk < 16; kk++) {
            float4 a0 = *(const float4*)&As[kk][tx * 8];
            float4 a1 = *(const float4*)&As[kk][tx * 8 + 4];
            float4 b4 = *(const float4*)&Bs[kk][ty * 4];
            float a[8] = {a0.x, a0.y, a0.z, a0.w, a1.x, a1.y, a1.z, a1.w};
            float bb[4] = {b4.x, b4.y, b4.z, b4.w};
            #pragma unroll
            for (int i = 0; i < 8; i++)
                #pragma unroll
                for (int j = 0; j < 4; j++) acc[i][j] += a[i] * bb[j];
        }
        __syncthreads();
    }

    // ---- epilogue: C[n][m], relu ----
    #pragma unroll
    for (int j = 0; j < 4; j++) {
        int n = n0 + ty * 4 + j;
        if (n < ncols) {
            float* Cc = C + (size_t)n * Mdim + m0 + tx * 8;
            float4 v0, v1;
            v0.x = fmaxf(acc[0][j], 0.f); v0.y = fmaxf(acc[1][j], 0.f);
            v0.z = fmaxf(acc[2][j], 0.f); v0.w = fmaxf(acc[3][j], 0.f);
            v1.x = fmaxf(acc[4][j], 0.f); v1.y = fmaxf(acc[5][j], 0.f);
            v1.z = fmaxf(acc[6][j], 0.f); v1.w = fmaxf(acc[7][j], 0.f);
            *(float4*)(Cc)     = v0;
            *(float4*)(Cc + 4) = v1;
        }
    }
}

// ============================================================
// K4: score[col] = sigmoid( W5 . H4[col] )   (compact col)
// ============================================================
__global__ void k_score(const float* __restrict__ W5) {
    int local = blockIdx.x, b = blockIdx.y;
    int nloc = 1 + g_nused;
    if (local >= nloc) return;
    int col = b * nloc + local;
    const float* h = &g_H4[(size_t)col * H2DIM];
    int tid = threadIdx.x;   // 128
    float acc = 0.f;
    for (int i = tid; i < H2DIM; i += 128) acc += W5[i] * h[i];
    #pragma unroll
    for (int o = 16; o; o >>= 1) acc += __shfl_down_sync(0xffffffffu, acc, o);
    __shared__ float sh[4];
    if ((tid & 31) == 0) sh[tid >> 5] = acc;
    __syncthreads();
    if (tid == 0) {
        float s = sh[0] + sh[1] + sh[2] + sh[3];
        g_score[col] = 1.f / (1.f + expf(-s));
    }
}

// ============================================================
// K5: loss = sum_b [ 128*(pos-1)^2 + sum_n score[...]^2 ]
// (permutation-invariant; perm_idx drops out exactly)
// ============================================================
__global__ void k_loss(const int* __restrict__ rand_idx, float* __restrict__ out) {
    int tid = threadIdx.x;   // 256
    int nloc = 1 + g_nused;
    float acc = 0.f;
    for (int idx = tid; idx < BATCH * NEG_N; idx += 256) {
        int b = idx >> 7, n = idx & 127;
        int s = rand_idx[n];
        s = min(max(s, 0), NSAMP - 1);
        int u = g_slot[s];                    // >=1 by construction
        float v = g_score[b * nloc + u];
        acc += v * v;
    }
    if (tid < BATCH) {
        float v = g_score[tid * nloc] - 1.f;
        acc += 128.f * v * v;
    }
    __shared__ float sh[256];
    sh[tid] = acc;
    __syncthreads();
    for (int o = 128; o; o >>= 1) {
        if (tid < o) sh[tid] += sh[tid + o];
        __syncthreads();
    }
    if (tid == 0) out[0] = sh[0];
}

// ============================================================
// launch
// ============================================================
extern "C" void kernel_launch(void* const* d_in, const int* in_sizes, int n_in,
                              void* d_out, int out_size) {
    const int*   doc       = (const int*)  d_in[0];
    const float* doc_f     = (const float*)d_in[1];
    const int*   query     = (const int*)  d_in[2];
    const int*   target_s  = (const int*)  d_in[3];
    const int*   target_e  = (const int*)  d_in[4];
    // d_in[5] doc_mask, d_in[6] query_mask: unused by reference
    const float* emb       = (const float*)d_in[7];
    const float* W1        = (const float*)d_in[8];
    const float* W2        = (const float*)d_in[9];
    const float* W3        = (const float*)d_in[10];
    const float* W4        = (const float*)d_in[11];
    const float* W5        = (const float*)d_in[12];
    const int*   rand_len  = (const int*)  d_in[13];
    const int*   rand_pos  = (const int*)  d_in[14];
    const int*   rand_idx  = (const int*)  d_in[15];
    // d_in[16] perm_idx: permutation-invariant loss -> unused
    float* out = (float*)d_out;

    float *F, *H1, *H2, *H3, *H4;
    cudaGetSymbolAddress((void**)&F,  g_F);
    cudaGetSymbolAddress((void**)&H1, g_H1);
    cudaGetSymbolAddress((void**)&H2, g_H2);
    cudaGetSymbolAddress((void**)&H3, g_H3);
    cudaGetSymbolAddress((void**)&H4, g_H4);

    k_prep<<<1, 256>>>(rand_idx);
    k_qf  <<<BATCH, 128>>>(query, emb);
    {
        dim3 g(NLOC, BATCH);
        k_feat<<<g, 256>>>(doc, doc_f, emb, target_s, target_e, rand_len, rand_pos);
    }
    {
        dim3 g1(HID / 128,   NTILES);
        dim3 g4(H2DIM / 128, NTILES);
        k_gemm<<<g1, 256>>>(W1, F,  H1, HID,   CIN);
        k_gemm<<<g1, 256>>>(W2, H1, H2, HID,   HID);
        k_gemm<<<g1, 256>>>(W3, H2, H3, HID,   HID);
        k_gemm<<<g4, 256>>>(W4, H3, H4, H2DIM, HID);
    }
    {
        dim3 g(NLOC, BATCH);
        k_score<<<g, 128>>>(W5);
    }
    k_loss<<<1, 256>>>(rand_idx, out);
}

// round 4
// speedup vs baseline: 5.7453x; 3.0995x over previous
#include <cuda_runtime.h>
#include <cuda_bf16.h>
#include <math.h>
#include <stdint.h>

typedef __nv_bfloat16 bf16;

// ----- problem constants -----
#define BATCH   32
#define LD      512
#define LQ      32
#define EDIM    300
#define NF      4
#define DDIM    304
#define MWIN    16
#define ALPHA   0.9f
#define HID     1024
#define H2DIM   512
#define CIN     1212
#define KP1     1216          // CIN padded to 64
#define PPL     9
#define NSAMP   144
#define NEG_N   128
#define NLOC    145
#define NCOL    (BATCH*NLOC)  // 4640 worst case
#define NCOLP   4704          // >= NTILES*64
#define NTILE   64
#define NTILES  ((NCOL + NTILE - 1) / NTILE)   // 73

// ----- scratch (device globals; no allocation allowed) -----
__device__ __align__(16) bf16 g_W1h[(size_t)HID*KP1],  g_W1l[(size_t)HID*KP1];
__device__ __align__(16) bf16 g_W2h[(size_t)HID*HID],  g_W2l[(size_t)HID*HID];
__device__ __align__(16) bf16 g_W3h[(size_t)HID*HID],  g_W3l[(size_t)HID*HID];
__device__ __align__(16) bf16 g_W4h[(size_t)H2DIM*HID],g_W4l[(size_t)H2DIM*HID];
__device__ __align__(16) bf16 g_Fh [(size_t)NCOLP*KP1], g_Fl [(size_t)NCOLP*KP1];
__device__ __align__(16) bf16 g_H1h[(size_t)NCOLP*HID], g_H1l[(size_t)NCOLP*HID];
__device__ __align__(16) bf16 g_H2h[(size_t)NCOLP*HID], g_H2l[(size_t)NCOLP*HID];
__device__ __align__(16) bf16 g_H3h[(size_t)NCOLP*HID], g_H3l[(size_t)NCOLP*HID];
__device__ __align__(16) float g_H4[(size_t)NCOLP*H2DIM];
__device__ float g_score[NCOLP];
__device__ float g_qf[BATCH*EDIM];
__device__ int   g_used[NSAMP];
__device__ int   g_slot[NSAMP];
__device__ int   g_nused;

// ============================================================
// helpers
// ============================================================
__device__ __forceinline__ uint32_t smem_u32(const void* p) {
    uint32_t a;
    asm("{ .reg .u64 t; cvta.to.shared.u64 t, %1; cvt.u32.u64 %0, t; }" : "=r"(a) : "l"(p));
    return a;
}
#define SWZ(b) ((b) ^ (((b) >> 3) & 0x70))

#define CP16(dst, src) asm volatile("cp.async.ca.shared.global [%0], [%1], 16;" :: "r"(dst), "l"(src))
#define CP_COMMIT()    asm volatile("cp.async.commit_group;" ::: "memory")
#define CP_WAIT(n)     asm volatile("cp.async.wait_group %0;" :: "n"(n) : "memory")

__device__ __forceinline__ void ldm_x4(uint32_t& r0, uint32_t& r1, uint32_t& r2,
                                       uint32_t& r3, uint32_t addr) {
    asm volatile("ldmatrix.sync.aligned.m8n8.x4.shared.b16 {%0,%1,%2,%3}, [%4];"
        : "=r"(r0), "=r"(r1), "=r"(r2), "=r"(r3) : "r"(addr));
}
__device__ __forceinline__ void mma_bf16(float* d, const uint32_t* a, const uint32_t* b) {
    asm volatile("mma.sync.aligned.m16n8k16.row.col.f32.bf16.bf16.f32 "
        "{%0,%1,%2,%3}, {%4,%5,%6,%7}, {%8,%9}, {%0,%1,%2,%3};"
        : "+f"(d[0]), "+f"(d[1]), "+f"(d[2]), "+f"(d[3])
        : "r"(a[0]), "r"(a[1]), "r"(a[2]), "r"(a[3]), "r"(b[0]), "r"(b[1]));
}

// ============================================================
// K0: dedup rand_idx -> used list + slot map (1 block)
// ============================================================
__global__ void k_prep(const int* __restrict__ rand_idx) {
    __shared__ int s_cnt[NSAMP];
    int tid = threadIdx.x;
    for (int i = tid; i < NSAMP; i += blockDim.x) s_cnt[i] = 0;
    __syncthreads();
    for (int n = tid; n < NEG_N; n += blockDim.x) {
        int s = rand_idx[n];
        s = min(max(s, 0), NSAMP - 1);
        atomicAdd(&s_cnt[s], 1);
    }
    __syncthreads();
    if (tid == 0) {
        int u = 0;
        for (int s = 0; s < NSAMP; s++) {
            if (s_cnt[s] > 0) { g_used[u] = s; g_slot[s] = u + 1; u++; }
            else              { g_slot[s] = 0; }
        }
        g_nused = u;
    }
}

// ============================================================
// K1: query FOFE vector
// ============================================================
__global__ void k_qf(const int* __restrict__ query, const float* __restrict__ emb) {
    int b = blockIdx.x;
    int tid = threadIdx.x;
    __shared__ float qw[LQ];
    __shared__ int   tok[LQ];
    if (tid < LQ) {
        float w = 1.f;
        for (int k = 0; k < LQ - 1 - tid; k++) w *= ALPHA;
        qw[tid]  = w;
        tok[tid] = query[b * LQ + tid];
    }
    __syncthreads();
    for (int e = tid; e < EDIM; e += blockDim.x) {
        float acc = 0.f;
        #pragma unroll 4
        for (int t = 0; t < LQ; t++)
            acc += qw[t] * emb[(size_t)tok[t] * EDIM + e];
        g_qf[b * EDIM + e] = acc;
    }
}

// ============================================================
// K2: build COMPACT feature matrix (bf16 hi/lo, K padded to KP1)
// ============================================================
__device__ __forceinline__ float doc_x(const int* doc, const float* doc_f,
                                       const float* emb, int b, int ch, int t) {
    if (ch < EDIM) {
        int tokv = doc[b * LD + t];
        return emb[(size_t)tokv * EDIM + ch];
    }
    return doc_f[((size_t)(b * LD + t)) * NF + (ch - EDIM)];
}

__global__ void k_feat(const int* __restrict__ doc, const float* __restrict__ doc_f,
                       const float* __restrict__ emb,
                       const int* __restrict__ target_s, const int* __restrict__ target_e,
                       const int* __restrict__ rand_length, const int* __restrict__ rand_position) {
    int local = blockIdx.x;
    int b     = blockIdx.y;
    int nloc  = 1 + g_nused;
    if (local >= nloc) return;

    int base_l, pos_a, ka, base_r;
    if (local == 0) {
        int ts = target_s[b], te = target_e[b];
        base_l = max(ts - 1, 0);
        pos_a  = min(max(te, 0), LD - 1);
        ka     = te - ts;
        base_r = min(te + 1, LD - 1);
    } else {
        int s  = g_used[local - 1];
        int i  = s / PPL, j = s % PPL;
        int rl = min(max(rand_length[i], 0), MWIN - 1);
        int p  = rand_position[i * PPL + j];
        p      = min(max(p, 0), LD - 1);
        pos_a  = p;
        ka     = rl;
        base_l = min(max(p - 1, 0), LD - 1);
        base_r = min(max(p + rl + 1, 0), LD - 1);
    }

    size_t row = (size_t)(b * nloc + local) * KP1;
    bf16* oh = &g_Fh[row];
    bf16* ol = &g_Fl[row];
    for (int c = threadIdx.x; c < KP1; c += blockDim.x) {
        float acc = 0.f;
        if (c < 3 * DDIM) {
            int seg = c / DDIM, ch = c % DDIM;
            float w = 1.f;
            if (seg == 0) {
                for (int k = 0; k <= MWIN - 1; k++) {
                    int t = base_l - k;
                    if (t >= 0) acc += w * doc_x(doc, doc_f, emb, b, ch, t);
                    w *= ALPHA;
                }
            } else if (seg == 1) {
                for (int k = 0; k <= ka; k++) {
                    int t = pos_a - k;
                    if (t >= 0) acc += w * doc_x(doc, doc_f, emb, b, ch, t);
                    w *= ALPHA;
                }
            } else {
                for (int k = 0; k <= MWIN - 1; k++) {
                    int t = base_r + k;
                    if (t < LD) acc += w * doc_x(doc, doc_f, emb, b, ch, t);
                    w *= ALPHA;
                }
            }
        } else if (c < CIN) {
            acc = g_qf[b * EDIM + (c - 3 * DDIM)];
        }
        bf16 h = __float2bfloat16(acc);
        oh[c] = h;
        ol[c] = __float2bfloat16(acc - __bfloat162float(h));
    }
}

// ============================================================
// K2b: weight -> bf16 hi/lo (with K zero-padding)
// ============================================================
__global__ void k_conv(const float* __restrict__ W, bf16* __restrict__ hi,
                       bf16* __restrict__ lo, int Mr, int K, int Kp) {
    int total = Mr * Kp;
    for (int idx = blockIdx.x * blockDim.x + threadIdx.x; idx < total;
         idx += gridDim.x * blockDim.x) {
        int r = idx / Kp, k = idx - r * Kp;
        float v = (k < K) ? W[(size_t)r * K + k] : 0.f;
        bf16 h = __float2bfloat16(v);
        hi[idx] = h;
        lo[idx] = __float2bfloat16(v - __bfloat162float(h));
    }
}

// ============================================================
// K3: bf16-split HMMA GEMM + ReLU.
//   D[m][n] = sum_k A[m][k]*B[n][k]; A = weights [Mdim x K], B = cols [n x K]
//   CTA tile 128x64, 8 warps (4M x 2N), warp tile 32x32 (2 x 4 m16n8 atoms).
//   K chunks of 64, cp.async double-buffered, SW128-swizzled SMEM + ldmatrix.
// ============================================================
#define OFF_AH 0
#define OFF_AL 16384
#define OFF_BH 32768
#define OFF_BL 40960
#define STAGE_BYTES 49152
#define SMEM_TOT (2*STAGE_BYTES)   // 98304

__device__ __forceinline__ void load_tile_cp(const bf16* __restrict__ G, int row0,
                                             int stride, int k0, uint32_t smd,
                                             int rows, int tid) {
    int nv = rows * 8;               // 16B vectors per tile row: 64 bf16 = 8
    for (int v = tid; v < nv; v += 256) {
        int r = v >> 3, seg = v & 7;
        const bf16* src = G + (size_t)(row0 + r) * stride + k0 + seg * 8;
        CP16(smd + SWZ(r * 128 + seg * 16), src);
    }
}

template<bool SPLIT>
__global__ __launch_bounds__(256, 1)
void k_tgemm(const bf16* __restrict__ Ah, const bf16* __restrict__ Al,
             const bf16* __restrict__ Bh, const bf16* __restrict__ Bl,
             bf16* __restrict__ Oh, bf16* __restrict__ Ol,
             float* __restrict__ O32, int Mdim, int K) {
    int ncols = BATCH * (1 + g_nused);
    int n0 = blockIdx.y * NTILE;
    if (n0 >= ncols) return;
    int m0 = blockIdx.x * 128;

    extern __shared__ __align__(128) char sm[];
    uint32_t smb = smem_u32(sm);
    int tid  = threadIdx.x;
    int wid  = tid >> 5, lane = tid & 31;
    int wm   = wid & 3;          // 4 warps over M (32 rows each)
    int wn   = wid >> 2;         // 2 warps over N (32 cols each)

    // ldmatrix lane address components
    int a_row_l = lane & 15;
    int a_off_l = (lane >> 4) << 4;               // 0 / 16
    int b_n_l   = ((lane >> 4) << 3) + (lane & 7);
    int b_off_l = ((lane >> 3) & 1) << 4;         // 0 / 16

    float acc[2][4][4];
    #pragma unroll
    for (int i = 0; i < 2; i++)
        #pragma unroll
        for (int j = 0; j < 4; j++)
            #pragma unroll
            for (int q = 0; q < 4; q++) acc[i][j][q] = 0.f;

    int nch = K >> 6;
    // prefetch chunk 0 -> stage 0
    {
        uint32_t sb = smb;
        load_tile_cp(Ah, m0, K, 0, sb + OFF_AH, 128, tid);
        load_tile_cp(Al, m0, K, 0, sb + OFF_AL, 128, tid);
        load_tile_cp(Bh, n0, K, 0, sb + OFF_BH, 64, tid);
        load_tile_cp(Bl, n0, K, 0, sb + OFF_BL, 64, tid);
        CP_COMMIT();
    }

    for (int c = 0; c < nch; c++) {
        if (c + 1 < nch) {
            uint32_t sb = smb + ((c + 1) & 1) * STAGE_BYTES;
            int k0 = (c + 1) << 6;
            load_tile_cp(Ah, m0, K, k0, sb + OFF_AH, 128, tid);
            load_tile_cp(Al, m0, K, k0, sb + OFF_AL, 128, tid);
            load_tile_cp(Bh, n0, K, k0, sb + OFF_BH, 64, tid);
            load_tile_cp(Bl, n0, K, k0, sb + OFF_BL, 64, tid);
            CP_COMMIT();
            CP_WAIT(1);
        } else {
            CP_WAIT(0);
        }
        __syncthreads();

        uint32_t sb = smb + (c & 1) * STAGE_BYTES;
        #pragma unroll
        for (int kk = 0; kk < 4; kk++) {
            int kb = kk << 5;   // 32 bytes per k16 step
            uint32_t ah[2][4], al[2][4], bh[2][4], bl[2][4];
            #pragma unroll
            for (int ma = 0; ma < 2; ma++) {
                uint32_t off = SWZ((wm * 32 + ma * 16 + a_row_l) * 128 + kb + a_off_l);
                ldm_x4(ah[ma][0], ah[ma][1], ah[ma][2], ah[ma][3], sb + OFF_AH + off);
                ldm_x4(al[ma][0], al[ma][1], al[ma][2], al[ma][3], sb + OFF_AL + off);
            }
            #pragma unroll
            for (int nb = 0; nb < 2; nb++) {
                uint32_t off = SWZ((wn * 32 + nb * 16 + b_n_l) * 128 + kb + b_off_l);
                ldm_x4(bh[nb][0], bh[nb][1], bh[nb][2], bh[nb][3], sb + OFF_BH + off);
                ldm_x4(bl[nb][0], bl[nb][1], bl[nb][2], bl[nb][3], sb + OFF_BL + off);
            }
            #pragma unroll
            for (int ma = 0; ma < 2; ma++) {
                #pragma unroll
                for (int na = 0; na < 4; na++) {
                    const uint32_t* pbh = &bh[na >> 1][(na & 1) * 2];
                    const uint32_t* pbl = &bl[na >> 1][(na & 1) * 2];
                    mma_bf16(acc[ma][na], ah[ma], pbh);
                    mma_bf16(acc[ma][na], ah[ma], pbl);
                    mma_bf16(acc[ma][na], al[ma], pbh);
                }
            }
        }
        __syncthreads();
    }

    // epilogue: relu + write O[n][m]
    #pragma unroll
    for (int ma = 0; ma < 2; ma++) {
        int mrow = m0 + wm * 32 + ma * 16 + (lane >> 2);
        #pragma unroll
        for (int na = 0; na < 4; na++) {
            int nb2 = n0 + wn * 32 + na * 8 + ((lane & 3) << 1);
            #pragma unroll
            for (int q = 0; q < 4; q++) {
                int n = nb2 + (q & 1);
                int m = mrow + ((q >> 1) << 3);
                if (n < ncols) {
                    float v = fmaxf(acc[ma][na][q], 0.f);
                    if (SPLIT) {
                        bf16 h = __float2bfloat16(v);
                        Oh[(size_t)n * Mdim + m] = h;
                        Ol[(size_t)n * Mdim + m] = __float2bfloat16(v - __bfloat162float(h));
                    } else {
                        O32[(size_t)n * Mdim + m] = v;
                    }
                }
            }
        }
    }
}

// ============================================================
// K4: score = sigmoid(W5 . H4)
// ============================================================
__global__ void k_score(const float* __restrict__ W5) {
    int local = blockIdx.x, b = blockIdx.y;
    int nloc = 1 + g_nused;
    if (local >= nloc) return;
    int col = b * nloc + local;
    const float* h = &g_H4[(size_t)col * H2DIM];
    int tid = threadIdx.x;
    float acc = 0.f;
    for (int i = tid; i < H2DIM; i += 128) acc += W5[i] * h[i];
    #pragma unroll
    for (int o = 16; o; o >>= 1) acc += __shfl_down_sync(0xffffffffu, acc, o);
    __shared__ float sh[4];
    if ((tid & 31) == 0) sh[tid >> 5] = acc;
    __syncthreads();
    if (tid == 0) {
        float s = sh[0] + sh[1] + sh[2] + sh[3];
        g_score[col] = 1.f / (1.f + expf(-s));
    }
}

// ============================================================
// K5: loss (permutation-invariant; perm_idx drops out)
// ============================================================
__global__ void k_loss(const int* __restrict__ rand_idx, float* __restrict__ out) {
    int tid = threadIdx.x;
    int nloc = 1 + g_nused;
    float acc = 0.f;
    for (int idx = tid; idx < BATCH * NEG_N; idx += 256) {
        int b = idx >> 7, n = idx & 127;
        int s = rand_idx[n];
        s = min(max(s, 0), NSAMP - 1);
        int u = g_slot[s];
        float v = g_score[b * nloc + u];
        acc += v * v;
    }
    if (tid < BATCH) {
        float v = g_score[tid * nloc] - 1.f;
        acc += 128.f * v * v;
    }
    __shared__ float sh[256];
    sh[tid] = acc;
    __syncthreads();
    for (int o = 128; o; o >>= 1) {
        if (tid < o) sh[tid] += sh[tid + o];
        __syncthreads();
    }
    if (tid == 0) out[0] = sh[0];
}

// ============================================================
// launch
// ============================================================
extern "C" void kernel_launch(void* const* d_in, const int* in_sizes, int n_in,
                              void* d_out, int out_size) {
    const int*   doc       = (const int*)  d_in[0];
    const float* doc_f     = (const float*)d_in[1];
    const int*   query     = (const int*)  d_in[2];
    const int*   target_s  = (const int*)  d_in[3];
    const int*   target_e  = (const int*)  d_in[4];
    const float* emb       = (const float*)d_in[7];
    const float* W1        = (const float*)d_in[8];
    const float* W2        = (const float*)d_in[9];
    const float* W3        = (const float*)d_in[10];
    const float* W4        = (const float*)d_in[11];
    const float* W5        = (const float*)d_in[12];
    const int*   rand_len  = (const int*)  d_in[13];
    const int*   rand_pos  = (const int*)  d_in[14];
    const int*   rand_idx  = (const int*)  d_in[15];
    float* out = (float*)d_out;

    bf16 *W1h,*W1l,*W2h,*W2l,*W3h,*W3l,*W4h,*W4l;
    bf16 *Fh,*Fl,*H1h,*H1l,*H2h,*H2l,*H3h,*H3l;
    float *H4;
    cudaGetSymbolAddress((void**)&W1h, g_W1h); cudaGetSymbolAddress((void**)&W1l, g_W1l);
    cudaGetSymbolAddress((void**)&W2h, g_W2h); cudaGetSymbolAddress((void**)&W2l, g_W2l);
    cudaGetSymbolAddress((void**)&W3h, g_W3h); cudaGetSymbolAddress((void**)&W3l, g_W3l);
    cudaGetSymbolAddress((void**)&W4h, g_W4h); cudaGetSymbolAddress((void**)&W4l, g_W4l);
    cudaGetSymbolAddress((void**)&Fh,  g_Fh);  cudaGetSymbolAddress((void**)&Fl,  g_Fl);
    cudaGetSymbolAddress((void**)&H1h, g_H1h); cudaGetSymbolAddress((void**)&H1l, g_H1l);
    cudaGetSymbolAddress((void**)&H2h, g_H2h); cudaGetSymbolAddress((void**)&H2l, g_H2l);
    cudaGetSymbolAddress((void**)&H3h, g_H3h); cudaGetSymbolAddress((void**)&H3l, g_H3l);
    cudaGetSymbolAddress((void**)&H4,  g_H4);

    cudaFuncSetAttribute(k_tgemm<true>,  cudaFuncAttributeMaxDynamicSharedMemorySize, SMEM_TOT);
    cudaFuncSetAttribute(k_tgemm<false>, cudaFuncAttributeMaxDynamicSharedMemorySize, SMEM_TOT);

    k_prep<<<1, 256>>>(rand_idx);
    k_qf  <<<BATCH, 128>>>(query, emb);
    k_conv<<<1024, 256>>>(W1, W1h, W1l, HID,   CIN, KP1);
    k_conv<<<1024, 256>>>(W2, W2h, W2l, HID,   HID, HID);
    k_conv<<<1024, 256>>>(W3, W3h, W3l, HID,   HID, HID);
    k_conv<<<512,  256>>>(W4, W4h, W4l, H2DIM, HID, HID);
    {
        dim3 g(NLOC, BATCH);
        k_feat<<<g, 256>>>(doc, doc_f, emb, target_s, target_e, rand_len, rand_pos);
    }
    {
        dim3 g1(HID / 128,   NTILES);
        dim3 g4(H2DIM / 128, NTILES);
        k_tgemm<true ><<<g1, 256, SMEM_TOT>>>(W1h, W1l, Fh,  Fl,  H1h, H1l, (float*)0, HID,   KP1);
        k_tgemm<true ><<<g1, 256, SMEM_TOT>>>(W2h, W2l, H1h, H1l, H2h, H2l, (float*)0, HID,   HID);
        k_tgemm<true ><<<g1, 256, SMEM_TOT>>>(W3h, W3l, H2h, H2l, H3h, H3l, (float*)0, HID,   HID);
        k_tgemm<false><<<g4, 256, SMEM_TOT>>>(W4h, W4l, H3h, H3l, (bf16*)0, (bf16*)0, H4, H2DIM, HID);
    }
    {
        dim3 g(NLOC, BATCH);
        k_score<<<g, 128>>>(W5);
    }
    k_loss<<<1, 256>>>(rand_idx, out);
}

// round 5
// speedup vs baseline: 5.9544x; 1.0364x over previous
#include <cuda_runtime.h>
#include <cuda_bf16.h>
#include <math.h>
#include <stdint.h>

typedef __nv_bfloat16 bf16;

// ----- problem constants -----
#define BATCH   32
#define LD      512
#define LQ      32
#define EDIM    300
#define NF      4
#define DDIM    304
#define MWIN    16
#define ALPHA   0.9f
#define HID     1024
#define H2DIM   512
#define CIN     1212
#define KP1     1216          // CIN padded to 64
#define PPL     9
#define NSAMP   144
#define NEG_N   128
#define NLOC    145
#define NCOL    (BATCH*NLOC)  // 4640 worst case
#define NCOLP   4704          // >= NTILES*64
#define NTILE   64
#define NTILES  ((NCOL + NTILE - 1) / NTILE)   // 73

// ----- scratch (device globals; no allocation allowed) -----
__device__ __align__(16) bf16 g_W1h[(size_t)HID*KP1],  g_W1l[(size_t)HID*KP1];
__device__ __align__(16) bf16 g_W2h[(size_t)HID*HID],  g_W2l[(size_t)HID*HID];
__device__ __align__(16) bf16 g_W3h[(size_t)HID*HID],  g_W3l[(size_t)HID*HID];
__device__ __align__(16) bf16 g_W4h[(size_t)H2DIM*HID],g_W4l[(size_t)H2DIM*HID];
__device__ __align__(16) bf16 g_Fh [(size_t)NCOLP*KP1], g_Fl [(size_t)NCOLP*KP1];
__device__ __align__(16) bf16 g_H1h[(size_t)NCOLP*HID], g_H1l[(size_t)NCOLP*HID];
__device__ __align__(16) bf16 g_H2h[(size_t)NCOLP*HID], g_H2l[(size_t)NCOLP*HID];
__device__ __align__(16) bf16 g_H3h[(size_t)NCOLP*HID], g_H3l[(size_t)NCOLP*HID];
__device__ __align__(16) float g_H4[(size_t)NCOLP*H2DIM];
__device__ float g_score[NCOLP];
__device__ float g_qf[BATCH*EDIM];
__device__ int   g_used[NSAMP];
__device__ int   g_slot[NSAMP];
__device__ int   g_nused;

// ============================================================
// helpers
// ============================================================
__device__ __forceinline__ uint32_t smem_u32(const void* p) {
    uint32_t a;
    asm("{ .reg .u64 t; cvta.to.shared.u64 t, %1; cvt.u32.u64 %0, t; }" : "=r"(a) : "l"(p));
    return a;
}
#define SWZ(b) ((b) ^ (((b) >> 3) & 0x70))

#define CP16(dst, src) asm volatile("cp.async.ca.shared.global [%0], [%1], 16;" :: "r"(dst), "l"(src))
#define CP_COMMIT()    asm volatile("cp.async.commit_group;" ::: "memory")
#define CP_WAIT(n)     asm volatile("cp.async.wait_group %0;" :: "n"(n) : "memory")

__device__ __forceinline__ void ldm_x4(uint32_t& r0, uint32_t& r1, uint32_t& r2,
                                       uint32_t& r3, uint32_t addr) {
    asm volatile("ldmatrix.sync.aligned.m8n8.x4.shared.b16 {%0,%1,%2,%3}, [%4];"
        : "=r"(r0), "=r"(r1), "=r"(r2), "=r"(r3) : "r"(addr));
}
__device__ __forceinline__ void mma_bf16(float* d, const uint32_t* a, const uint32_t* b) {
    asm volatile("mma.sync.aligned.m16n8k16.row.col.f32.bf16.bf16.f32 "
        "{%0,%1,%2,%3}, {%4,%5,%6,%7}, {%8,%9}, {%0,%1,%2,%3};"
        : "+f"(d[0]), "+f"(d[1]), "+f"(d[2]), "+f"(d[3])
        : "r"(a[0]), "r"(a[1]), "r"(a[2]), "r"(a[3]), "r"(b[0]), "r"(b[1]));
}

// ============================================================
// K0: dedup rand_idx -> used list + slot map (1 block)
// ============================================================
__global__ void k_prep(const int* __restrict__ rand_idx) {
    __shared__ int s_cnt[NSAMP];
    int tid = threadIdx.x;
    for (int i = tid; i < NSAMP; i += blockDim.x) s_cnt[i] = 0;
    __syncthreads();
    for (int n = tid; n < NEG_N; n += blockDim.x) {
        int s = rand_idx[n];
        s = min(max(s, 0), NSAMP - 1);
        atomicAdd(&s_cnt[s], 1);
    }
    __syncthreads();
    if (tid == 0) {
        int u = 0;
        for (int s = 0; s < NSAMP; s++) {
            if (s_cnt[s] > 0) { g_used[u] = s; g_slot[s] = u + 1; u++; }
            else              { g_slot[s] = 0; }
        }
        g_nused = u;
    }
}

// ============================================================
// K1: query FOFE vector
// ============================================================
__global__ void k_qf(const int* __restrict__ query, const float* __restrict__ emb) {
    int b = blockIdx.x;
    int tid = threadIdx.x;
    __shared__ float qw[LQ];
    __shared__ int   tok[LQ];
    if (tid < LQ) {
        float w = 1.f;
        for (int k = 0; k < LQ - 1 - tid; k++) w *= ALPHA;
        qw[tid]  = w;
        tok[tid] = query[b * LQ + tid];
    }
    __syncthreads();
    for (int e = tid; e < EDIM; e += blockDim.x) {
        float acc = 0.f;
        #pragma unroll 4
        for (int t = 0; t < LQ; t++)
            acc += qw[t] * emb[(size_t)tok[t] * EDIM + e];
        g_qf[b * EDIM + e] = acc;
    }
}

// ============================================================
// K2: build COMPACT feature matrix (bf16 hi/lo, K padded to KP1)
// ============================================================
__device__ __forceinline__ float doc_x(const int* doc, const float* doc_f,
                                       const float* emb, int b, int ch, int t) {
    if (ch < EDIM) {
        int tokv = doc[b * LD + t];
        return emb[(size_t)tokv * EDIM + ch];
    }
    return doc_f[((size_t)(b * LD + t)) * NF + (ch - EDIM)];
}

__global__ void k_feat(const int* __restrict__ doc, const float* __restrict__ doc_f,
                       const float* __restrict__ emb,
                       const int* __restrict__ target_s, const int* __restrict__ target_e,
                       const int* __restrict__ rand_length, const int* __restrict__ rand_position) {
    int local = blockIdx.x;
    int b     = blockIdx.y;
    int nloc  = 1 + g_nused;
    if (local >= nloc) return;

    int base_l, pos_a, ka, base_r;
    if (local == 0) {
        int ts = target_s[b], te = target_e[b];
        base_l = max(ts - 1, 0);
        pos_a  = min(max(te, 0), LD - 1);
        ka     = te - ts;
        base_r = min(te + 1, LD - 1);
    } else {
        int s  = g_used[local - 1];
        int i  = s / PPL, j = s % PPL;
        int rl = min(max(rand_length[i], 0), MWIN - 1);
        int p  = rand_position[i * PPL + j];
        p      = min(max(p, 0), LD - 1);
        pos_a  = p;
        ka     = rl;
        base_l = min(max(p - 1, 0), LD - 1);
        base_r = min(max(p + rl + 1, 0), LD - 1);
    }

    size_t row = (size_t)(b * nloc + local) * KP1;
    bf16* oh = &g_Fh[row];
    bf16* ol = &g_Fl[row];
    for (int c = threadIdx.x; c < KP1; c += blockDim.x) {
        float acc = 0.f;
        if (c < 3 * DDIM) {
            int seg = c / DDIM, ch = c % DDIM;
            float w = 1.f;
            if (seg == 0) {
                for (int k = 0; k <= MWIN - 1; k++) {
                    int t = base_l - k;
                    if (t >= 0) acc += w * doc_x(doc, doc_f, emb, b, ch, t);
                    w *= ALPHA;
                }
            } else if (seg == 1) {
                for (int k = 0; k <= ka; k++) {
                    int t = pos_a - k;
                    if (t >= 0) acc += w * doc_x(doc, doc_f, emb, b, ch, t);
                    w *= ALPHA;
                }
            } else {
                for (int k = 0; k <= MWIN - 1; k++) {
                    int t = base_r + k;
                    if (t < LD) acc += w * doc_x(doc, doc_f, emb, b, ch, t);
                    w *= ALPHA;
                }
            }
        } else if (c < CIN) {
            acc = g_qf[b * EDIM + (c - 3 * DDIM)];
        }
        bf16 h = __float2bfloat16(acc);
        oh[c] = h;
        ol[c] = __float2bfloat16(acc - __bfloat162float(h));
    }
}

// ============================================================
// K2b: all-weights -> bf16 hi/lo (single launch; gridDim.y = weight id)
// ============================================================
__global__ void k_conv4(const float* __restrict__ Wa, const float* __restrict__ Wb,
                        const float* __restrict__ Wc, const float* __restrict__ Wd,
                        bf16* __restrict__ ha, bf16* __restrict__ la,
                        bf16* __restrict__ hb, bf16* __restrict__ lb,
                        bf16* __restrict__ hc, bf16* __restrict__ lc,
                        bf16* __restrict__ hd, bf16* __restrict__ ld_) {
    int which = blockIdx.y;
    const float* W; bf16 *hi, *lo; int Mr, K, Kp;
    if      (which == 0) { W = Wa; hi = ha; lo = la; Mr = HID;   K = CIN; Kp = KP1; }
    else if (which == 1) { W = Wb; hi = hb; lo = lb; Mr = HID;   K = HID; Kp = HID; }
    else if (which == 2) { W = Wc; hi = hc; lo = lc; Mr = HID;   K = HID; Kp = HID; }
    else                 { W = Wd; hi = hd; lo = ld_; Mr = H2DIM; K = HID; Kp = HID; }

    if (K == Kp) {
        // vectorized: 4 floats -> 4 hi bf16 (8B) + 4 lo bf16 (8B)
        int total4 = (Mr * Kp) >> 2;
        for (int v = blockIdx.x * blockDim.x + threadIdx.x; v < total4;
             v += gridDim.x * blockDim.x) {
            float4 f = *(const float4*)(W + (size_t)v * 4);
            bf16 h0 = __float2bfloat16(f.x), h1 = __float2bfloat16(f.y);
            bf16 h2 = __float2bfloat16(f.z), h3 = __float2bfloat16(f.w);
            bf16 l0 = __float2bfloat16(f.x - __bfloat162float(h0));
            bf16 l1 = __float2bfloat16(f.y - __bfloat162float(h1));
            bf16 l2 = __float2bfloat16(f.z - __bfloat162float(h2));
            bf16 l3 = __float2bfloat16(f.w - __bfloat162float(h3));
            bf16 hv[4] = {h0, h1, h2, h3};
            bf16 lv[4] = {l0, l1, l2, l3};
            *(uint2*)(hi + (size_t)v * 4) = *(uint2*)hv;
            *(uint2*)(lo + (size_t)v * 4) = *(uint2*)lv;
        }
    } else {
        int total = Mr * Kp;
        for (int idx = blockIdx.x * blockDim.x + threadIdx.x; idx < total;
             idx += gridDim.x * blockDim.x) {
            int r = idx / Kp, k = idx - r * Kp;
            float v = (k < K) ? W[(size_t)r * K + k] : 0.f;
            bf16 h = __float2bfloat16(v);
            hi[idx] = h;
            lo[idx] = __float2bfloat16(v - __bfloat162float(h));
        }
    }
}

// ============================================================
// K3: bf16-split HMMA GEMM + ReLU.
//   D[m][n] = sum_k A[m][k]*B[n][k]; A = weights [Mdim x K], B = cols [n x K]
//   CTA tile 128x64, 8 warps (4M x 2N), warp tile 32x32 (2 x 4 m16n8 atoms).
//   K chunks of 64, cp.async double-buffered, SW128-swizzled SMEM + ldmatrix.
//   2 CTAs/SM (2 x 96KB SMEM fits in 228KB) for latency hiding.
// ============================================================
#define OFF_AH 0
#define OFF_AL 16384
#define OFF_BH 32768
#define OFF_BL 40960
#define STAGE_BYTES 49152
#define SMEM_TOT (2*STAGE_BYTES)   // 98304

__device__ __forceinline__ void load_tile_cp(const bf16* __restrict__ G, int row0,
                                             int stride, int k0, uint32_t smd,
                                             int rows, int tid) {
    int nv = rows * 8;               // 16B vectors per tile row: 64 bf16 = 8
    for (int v = tid; v < nv; v += 256) {
        int r = v >> 3, seg = v & 7;
        const bf16* src = G + (size_t)(row0 + r) * stride + k0 + seg * 8;
        CP16(smd + SWZ(r * 128 + seg * 16), src);
    }
}

template<bool SPLIT>
__global__ __launch_bounds__(256, 2)
void k_tgemm(const bf16* __restrict__ Ah, const bf16* __restrict__ Al,
             const bf16* __restrict__ Bh, const bf16* __restrict__ Bl,
             bf16* __restrict__ Oh, bf16* __restrict__ Ol,
             float* __restrict__ O32, int Mdim, int K) {
    int ncols = BATCH * (1 + g_nused);
    int n0 = blockIdx.y * NTILE;
    if (n0 >= ncols) return;
    int m0 = blockIdx.x * 128;

    extern __shared__ __align__(128) char sm[];
    uint32_t smb = smem_u32(sm);
    int tid  = threadIdx.x;
    int wid  = tid >> 5, lane = tid & 31;
    int wm   = wid & 3;          // 4 warps over M (32 rows each)
    int wn   = wid >> 2;         // 2 warps over N (32 cols each)

    // ldmatrix lane address components
    int a_row_l = lane & 15;
    int a_off_l = (lane >> 4) << 4;               // 0 / 16
    int b_n_l   = ((lane >> 4) << 3) + (lane & 7);
    int b_off_l = ((lane >> 3) & 1) << 4;         // 0 / 16

    float acc[2][4][4];
    #pragma unroll
    for (int i = 0; i < 2; i++)
        #pragma unroll
        for (int j = 0; j < 4; j++)
            #pragma unroll
            for (int q = 0; q < 4; q++) acc[i][j][q] = 0.f;

    int nch = K >> 6;
    // prefetch chunk 0 -> stage 0
    {
        uint32_t sb = smb;
        load_tile_cp(Ah, m0, K, 0, sb + OFF_AH, 128, tid);
        load_tile_cp(Al, m0, K, 0, sb + OFF_AL, 128, tid);
        load_tile_cp(Bh, n0, K, 0, sb + OFF_BH, 64, tid);
        load_tile_cp(Bl, n0, K, 0, sb + OFF_BL, 64, tid);
        CP_COMMIT();
    }

    for (int c = 0; c < nch; c++) {
        if (c + 1 < nch) {
            uint32_t sb = smb + ((c + 1) & 1) * STAGE_BYTES;
            int k0 = (c + 1) << 6;
            load_tile_cp(Ah, m0, K, k0, sb + OFF_AH, 128, tid);
            load_tile_cp(Al, m0, K, k0, sb + OFF_AL, 128, tid);
            load_tile_cp(Bh, n0, K, k0, sb + OFF_BH, 64, tid);
            load_tile_cp(Bl, n0, K, k0, sb + OFF_BL, 64, tid);
            CP_COMMIT();
            CP_WAIT(1);
        } else {
            CP_WAIT(0);
        }
        __syncthreads();

        uint32_t sb = smb + (c & 1) * STAGE_BYTES;
        #pragma unroll
        for (int kk = 0; kk < 4; kk++) {
            int kb = kk << 5;   // 32 bytes per k16 step
            uint32_t ah[2][4], al[2][4], bh[2][4], bl[2][4];
            #pragma unroll
            for (int ma = 0; ma < 2; ma++) {
                uint32_t off = SWZ((wm * 32 + ma * 16 + a_row_l) * 128 + kb + a_off_l);
                ldm_x4(ah[ma][0], ah[ma][1], ah[ma][2], ah[ma][3], sb + OFF_AH + off);
                ldm_x4(al[ma][0], al[ma][1], al[ma][2], al[ma][3], sb + OFF_AL + off);
            }
            #pragma unroll
            for (int nb = 0; nb < 2; nb++) {
                uint32_t off = SWZ((wn * 32 + nb * 16 + b_n_l) * 128 + kb + b_off_l);
                ldm_x4(bh[nb][0], bh[nb][1], bh[nb][2], bh[nb][3], sb + OFF_BH + off);
                ldm_x4(bl[nb][0], bl[nb][1], bl[nb][2], bl[nb][3], sb + OFF_BL + off);
            }
            #pragma unroll
            for (int ma = 0; ma < 2; ma++) {
                #pragma unroll
                for (int na = 0; na < 4; na++) {
                    const uint32_t* pbh = &bh[na >> 1][(na & 1) * 2];
                    const uint32_t* pbl = &bl[na >> 1][(na & 1) * 2];
                    mma_bf16(acc[ma][na], ah[ma], pbh);
                    mma_bf16(acc[ma][na], ah[ma], pbl);
                    mma_bf16(acc[ma][na], al[ma], pbh);
                }
            }
        }
        __syncthreads();
    }

    // epilogue: relu + write O[n][m]
    #pragma unroll
    for (int ma = 0; ma < 2; ma++) {
        int mrow = m0 + wm * 32 + ma * 16 + (lane >> 2);
        #pragma unroll
        for (int na = 0; na < 4; na++) {
            int nb2 = n0 + wn * 32 + na * 8 + ((lane & 3) << 1);
            #pragma unroll
            for (int q = 0; q < 4; q++) {
                int n = nb2 + (q & 1);
                int m = mrow + ((q >> 1) << 3);
                if (n < ncols) {
                    float v = fmaxf(acc[ma][na][q], 0.f);
                    if (SPLIT) {
                        bf16 h = __float2bfloat16(v);
                        Oh[(size_t)n * Mdim + m] = h;
                        Ol[(size_t)n * Mdim + m] = __float2bfloat16(v - __bfloat162float(h));
                    } else {
                        O32[(size_t)n * Mdim + m] = v;
                    }
                }
            }
        }
    }
}

// ============================================================
// K4: score = sigmoid(W5 . H4)
// ============================================================
__global__ void k_score(const float* __restrict__ W5) {
    int local = blockIdx.x, b = blockIdx.y;
    int nloc = 1 + g_nused;
    if (local >= nloc) return;
    int col = b * nloc + local;
    const float* h = &g_H4[(size_t)col * H2DIM];
    int tid = threadIdx.x;
    float acc = 0.f;
    for (int i = tid; i < H2DIM; i += 128) acc += W5[i] * h[i];
    #pragma unroll
    for (int o = 16; o; o >>= 1) acc += __shfl_down_sync(0xffffffffu, acc, o);
    __shared__ float sh[4];
    if ((tid & 31) == 0) sh[tid >> 5] = acc;
    __syncthreads();
    if (tid == 0) {
        float s = sh[0] + sh[1] + sh[2] + sh[3];
        g_score[col] = 1.f / (1.f + expf(-s));
    }
}

// ============================================================
// K5: loss (permutation-invariant; perm_idx drops out)
// ============================================================
__global__ void k_loss(const int* __restrict__ rand_idx, float* __restrict__ out) {
    int tid = threadIdx.x;
    int nloc = 1 + g_nused;
    float acc = 0.f;
    for (int idx = tid; idx < BATCH * NEG_N; idx += 256) {
        int b = idx >> 7, n = idx & 127;
        int s = rand_idx[n];
        s = min(max(s, 0), NSAMP - 1);
        int u = g_slot[s];
        float v = g_score[b * nloc + u];
        acc += v * v;
    }
    if (tid < BATCH) {
        float v = g_score[tid * nloc] - 1.f;
        acc += 128.f * v * v;
    }
    __shared__ float sh[256];
    sh[tid] = acc;
    __syncthreads();
    for (int o = 128; o; o >>= 1) {
        if (tid < o) sh[tid] += sh[tid + o];
        __syncthreads();
    }
    if (tid == 0) out[0] = sh[0];
}

// ============================================================
// launch
// ============================================================
extern "C" void kernel_launch(void* const* d_in, const int* in_sizes, int n_in,
                              void* d_out, int out_size) {
    const int*   doc       = (const int*)  d_in[0];
    const float* doc_f     = (const float*)d_in[1];
    const int*   query     = (const int*)  d_in[2];
    const int*   target_s  = (const int*)  d_in[3];
    const int*   target_e  = (const int*)  d_in[4];
    const float* emb       = (const float*)d_in[7];
    const float* W1        = (const float*)d_in[8];
    const float* W2        = (const float*)d_in[9];
    const float* W3        = (const float*)d_in[10];
    const float* W4        = (const float*)d_in[11];
    const float* W5        = (const float*)d_in[12];
    const int*   rand_len  = (const int*)  d_in[13];
    const int*   rand_pos  = (const int*)  d_in[14];
    const int*   rand_idx  = (const int*)  d_in[15];
    float* out = (float*)d_out;

    bf16 *W1h,*W1l,*W2h,*W2l,*W3h,*W3l,*W4h,*W4l;
    bf16 *Fh,*Fl,*H1h,*H1l,*H2h,*H2l,*H3h,*H3l;
    float *H4;
    cudaGetSymbolAddress((void**)&W1h, g_W1h); cudaGetSymbolAddress((void**)&W1l, g_W1l);
    cudaGetSymbolAddress((void**)&W2h, g_W2h); cudaGetSymbolAddress((void**)&W2l, g_W2l);
    cudaGetSymbolAddress((void**)&W3h, g_W3h); cudaGetSymbolAddress((void**)&W3l, g_W3l);
    cudaGetSymbolAddress((void**)&W4h, g_W4h); cudaGetSymbolAddress((void**)&W4l, g_W4l);
    cudaGetSymbolAddress((void**)&Fh,  g_Fh);  cudaGetSymbolAddress((void**)&Fl,  g_Fl);
    cudaGetSymbolAddress((void**)&H1h, g_H1h); cudaGetSymbolAddress((void**)&H1l, g_H1l);
    cudaGetSymbolAddress((void**)&H2h, g_H2h); cudaGetSymbolAddress((void**)&H2l, g_H2l);
    cudaGetSymbolAddress((void**)&H3h, g_H3h); cudaGetSymbolAddress((void**)&H3l, g_H3l);
    cudaGetSymbolAddress((void**)&H4,  g_H4);

    cudaFuncSetAttribute(k_tgemm<true>,  cudaFuncAttributeMaxDynamicSharedMemorySize, SMEM_TOT);
    cudaFuncSetAttribute(k_tgemm<false>, cudaFuncAttributeMaxDynamicSharedMemorySize, SMEM_TOT);

    k_prep<<<1, 256>>>(rand_idx);
    k_qf  <<<BATCH, 128>>>(query, emb);
    {
        dim3 gc(512, 4);
        k_conv4<<<gc, 256>>>(W1, W2, W3, W4,
                             W1h, W1l, W2h, W2l, W3h, W3l, W4h, W4l);
    }
    {
        dim3 g(NLOC, BATCH);
        k_feat<<<g, 256>>>(doc, doc_f, emb, target_s, target_e, rand_len, rand_pos);
    }
    {
        dim3 g1(HID / 128,   NTILES);
        dim3 g4(H2DIM / 128, NTILES);
        k_tgemm<true ><<<g1, 256, SMEM_TOT>>>(W1h, W1l, Fh,  Fl,  H1h, H1l, (float*)0, HID,   KP1);
        k_tgemm<true ><<<g1, 256, SMEM_TOT>>>(W2h, W2l, H1h, H1l, H2h, H2l, (float*)0, HID,   HID);
        k_tgemm<true ><<<g1, 256, SMEM_TOT>>>(W3h, W3l, H2h, H2l, H3h, H3l, (float*)0, HID,   HID);
        k_tgemm<false><<<g4, 256, SMEM_TOT>>>(W4h, W4l, H3h, H3l, (bf16*)0, (bf16*)0, H4, H2DIM, HID);
    }
    {
        dim3 g(NLOC, BATCH);
        k_score<<<g, 128>>>(W5);
    }
    k_loss<<<1, 256>>>(rand_idx, out);
}

// round 6
// speedup vs baseline: 6.6990x; 1.1251x over previous
#include <cuda_runtime.h>
#include <cuda_bf16.h>
#include <math.h>
#include <stdint.h>

typedef __nv_bfloat16 bf16;

// ----- problem constants -----
#define BATCH   32
#define LD      512
#define LQ      32
#define EDIM    300
#define NF      4
#define DDIM    304
#define MWIN    16
#define ALPHA   0.9f
#define HID     1024
#define H2DIM   512
#define CIN     1212
#define KP1     1216          // CIN padded to 64
#define PPL     9
#define NSAMP   144
#define NEG_N   128
#define NLOC    145
#define NCOL    (BATCH*NLOC)  // 4640 worst case
#define NCOLP   4704          // >= NTILES*64
#define NTILE   64
#define NTILES  ((NCOL + NTILE - 1) / NTILE)   // 73

// ----- scratch (device globals; no allocation allowed) -----
__device__ __align__(16) bf16 g_W1h[(size_t)HID*KP1],  g_W1l[(size_t)HID*KP1];
__device__ __align__(16) bf16 g_W2h[(size_t)HID*HID],  g_W2l[(size_t)HID*HID];
__device__ __align__(16) bf16 g_W3h[(size_t)HID*HID],  g_W3l[(size_t)HID*HID];
__device__ __align__(16) bf16 g_W4h[(size_t)H2DIM*HID],g_W4l[(size_t)H2DIM*HID];
__device__ __align__(16) bf16 g_Fh [(size_t)NCOLP*KP1], g_Fl [(size_t)NCOLP*KP1];
__device__ __align__(16) bf16 g_H1h[(size_t)NCOLP*HID], g_H1l[(size_t)NCOLP*HID];
__device__ __align__(16) bf16 g_H2h[(size_t)NCOLP*HID], g_H2l[(size_t)NCOLP*HID];
__device__ __align__(16) bf16 g_H3h[(size_t)NCOLP*HID], g_H3l[(size_t)NCOLP*HID];
__device__ float g_dotp[4*NCOLP];   // per-mblock partial W5.relu(h4)
__device__ float g_score[NCOLP];
__device__ float g_qf[BATCH*EDIM];
__device__ int   g_used[NSAMP];
__device__ int   g_slot[NSAMP];
__device__ int   g_nused;

// ============================================================
// helpers
// ============================================================
__device__ __forceinline__ uint32_t smem_u32(const void* p) {
    uint32_t a;
    asm("{ .reg .u64 t; cvta.to.shared.u64 t, %1; cvt.u32.u64 %0, t; }" : "=r"(a) : "l"(p));
    return a;
}
#define SWZ(b) ((b) ^ (((b) >> 3) & 0x70))

#define CP16(dst, src) asm volatile("cp.async.ca.shared.global [%0], [%1], 16;" :: "r"(dst), "l"(src))
#define CP_COMMIT()    asm volatile("cp.async.commit_group;" ::: "memory")
#define CP_WAIT(n)     asm volatile("cp.async.wait_group %0;" :: "n"(n) : "memory")

__device__ __forceinline__ void ldm_x4(uint32_t& r0, uint32_t& r1, uint32_t& r2,
                                       uint32_t& r3, uint32_t addr) {
    asm volatile("ldmatrix.sync.aligned.m8n8.x4.shared.b16 {%0,%1,%2,%3}, [%4];"
        : "=r"(r0), "=r"(r1), "=r"(r2), "=r"(r3) : "r"(addr));
}
__device__ __forceinline__ void mma_bf16(float* d, const uint32_t* a, const uint32_t* b) {
    asm volatile("mma.sync.aligned.m16n8k16.row.col.f32.bf16.bf16.f32 "
        "{%0,%1,%2,%3}, {%4,%5,%6,%7}, {%8,%9}, {%0,%1,%2,%3};"
        : "+f"(d[0]), "+f"(d[1]), "+f"(d[2]), "+f"(d[3])
        : "r"(a[0]), "r"(a[1]), "r"(a[2]), "r"(a[3]), "r"(b[0]), "r"(b[1]));
}

// ============================================================
// K0: dedup rand_idx -> used list + slot map (1 block)
// ============================================================
__global__ void k_prep(const int* __restrict__ rand_idx) {
    __shared__ int s_cnt[NSAMP];
    int tid = threadIdx.x;
    for (int i = tid; i < NSAMP; i += blockDim.x) s_cnt[i] = 0;
    __syncthreads();
    for (int n = tid; n < NEG_N; n += blockDim.x) {
        int s = rand_idx[n];
        s = min(max(s, 0), NSAMP - 1);
        atomicAdd(&s_cnt[s], 1);
    }
    __syncthreads();
    if (tid == 0) {
        int u = 0;
        for (int s = 0; s < NSAMP; s++) {
            if (s_cnt[s] > 0) { g_used[u] = s; g_slot[s] = u + 1; u++; }
            else              { g_slot[s] = 0; }
        }
        g_nused = u;
    }
}

// ============================================================
// K1: query FOFE vector
// ============================================================
__global__ void k_qf(const int* __restrict__ query, const float* __restrict__ emb) {
    int b = blockIdx.x;
    int tid = threadIdx.x;
    __shared__ float qw[LQ];
    __shared__ int   tok[LQ];
    if (tid < LQ) {
        float w = 1.f;
        for (int k = 0; k < LQ - 1 - tid; k++) w *= ALPHA;
        qw[tid]  = w;
        tok[tid] = query[b * LQ + tid];
    }
    __syncthreads();
    for (int e = tid; e < EDIM; e += blockDim.x) {
        float acc = 0.f;
        #pragma unroll 4
        for (int t = 0; t < LQ; t++)
            acc += qw[t] * emb[(size_t)tok[t] * EDIM + e];
        g_qf[b * EDIM + e] = acc;
    }
}

// ============================================================
// K2: build COMPACT feature matrix (bf16 hi/lo, K padded to KP1)
//   Tokens/weights for the 3 FOFE windows precomputed into shared;
//   per-channel 16-term sum fully unrolled -> MLP 16.
// ============================================================
__global__ void k_feat(const int* __restrict__ doc, const float* __restrict__ doc_f,
                       const float* __restrict__ emb,
                       const int* __restrict__ target_s, const int* __restrict__ target_e,
                       const int* __restrict__ rand_length, const int* __restrict__ rand_position) {
    int local = blockIdx.x;
    int b     = blockIdx.y;
    int nloc  = 1 + g_nused;
    if (local >= nloc) return;

    __shared__ int   stok[3][16];
    __shared__ int   spos[3][16];
    __shared__ float sw[3][16];
    __shared__ float sdf[3][4];

    int tid = threadIdx.x;

    int base_l, pos_a, ka, base_r;
    if (local == 0) {
        int ts = target_s[b], te = target_e[b];
        base_l = max(ts - 1, 0);
        pos_a  = min(max(te, 0), LD - 1);
        ka     = te - ts;
        base_r = min(te + 1, LD - 1);
    } else {
        int s  = g_used[local - 1];
        int i  = s / PPL, j = s % PPL;
        int rl = min(max(rand_length[i], 0), MWIN - 1);
        int p  = rand_position[i * PPL + j];
        p      = min(max(p, 0), LD - 1);
        pos_a  = p;
        ka     = rl;
        base_l = min(max(p - 1, 0), LD - 1);
        base_r = min(max(p + rl + 1, 0), LD - 1);
    }

    if (tid < 48) {
        int seg = tid >> 4, k = tid & 15;
        float w = 1.f;
        for (int i = 0; i < k; i++) w *= ALPHA;
        int t; bool valid;
        if (seg == 0)      { t = base_l - k; valid = (t >= 0); }
        else if (seg == 1) { t = pos_a - k; valid = (t >= 0) && (k <= ka); }
        else               { t = base_r + k; valid = (t < LD); }
        int tc = min(max(t, 0), LD - 1);
        sw[seg][k]   = valid ? w : 0.f;
        stok[seg][k] = valid ? doc[b * LD + tc] : 0;
        spos[seg][k] = tc;
    }
    __syncthreads();
    if (tid < 12) {
        int seg = tid >> 2, f = tid & 3;
        float acc = 0.f;
        #pragma unroll
        for (int k = 0; k < 16; k++)
            acc += sw[seg][k] * doc_f[((size_t)(b * LD + spos[seg][k])) * NF + f];
        sdf[seg][f] = acc;
    }
    __syncthreads();

    size_t row = (size_t)(b * nloc + local) * KP1;
    for (int c = tid; c < KP1; c += blockDim.x) {
        float acc = 0.f;
        if (c < 3 * DDIM) {
            int seg = (c >= 2 * DDIM) ? 2 : ((c >= DDIM) ? 1 : 0);
            int ch = c - seg * DDIM;
            if (ch < EDIM) {
                #pragma unroll
                for (int k = 0; k < 16; k++)
                    acc += sw[seg][k] * emb[(size_t)stok[seg][k] * EDIM + ch];
            } else {
                acc = sdf[seg][ch - EDIM];
            }
        } else if (c < CIN) {
            acc = g_qf[b * EDIM + (c - 3 * DDIM)];
        }
        bf16 h = __float2bfloat16(acc);
        g_Fh[row + c] = h;
        g_Fl[row + c] = __float2bfloat16(acc - __bfloat162float(h));
    }
}

// ============================================================
// K2b: all-weights -> bf16 hi/lo (single launch; gridDim.y = weight id)
// ============================================================
__global__ void k_conv4(const float* __restrict__ Wa, const float* __restrict__ Wb,
                        const float* __restrict__ Wc, const float* __restrict__ Wd,
                        bf16* __restrict__ ha, bf16* __restrict__ la,
                        bf16* __restrict__ hb, bf16* __restrict__ lb,
                        bf16* __restrict__ hc, bf16* __restrict__ lc,
                        bf16* __restrict__ hd, bf16* __restrict__ ld_) {
    int which = blockIdx.y;
    const float* W; bf16 *hi, *lo; int Mr, K, Kp;
    if      (which == 0) { W = Wa; hi = ha; lo = la; Mr = HID;   K = CIN; Kp = KP1; }
    else if (which == 1) { W = Wb; hi = hb; lo = lb; Mr = HID;   K = HID; Kp = HID; }
    else if (which == 2) { W = Wc; hi = hc; lo = lc; Mr = HID;   K = HID; Kp = HID; }
    else                 { W = Wd; hi = hd; lo = ld_; Mr = H2DIM; K = HID; Kp = HID; }

    if (K == Kp) {
        int total4 = (Mr * Kp) >> 2;
        for (int v = blockIdx.x * blockDim.x + threadIdx.x; v < total4;
             v += gridDim.x * blockDim.x) {
            float4 f = *(const float4*)(W + (size_t)v * 4);
            bf16 h0 = __float2bfloat16(f.x), h1 = __float2bfloat16(f.y);
            bf16 h2 = __float2bfloat16(f.z), h3 = __float2bfloat16(f.w);
            bf16 l0 = __float2bfloat16(f.x - __bfloat162float(h0));
            bf16 l1 = __float2bfloat16(f.y - __bfloat162float(h1));
            bf16 l2 = __float2bfloat16(f.z - __bfloat162float(h2));
            bf16 l3 = __float2bfloat16(f.w - __bfloat162float(h3));
            bf16 hv[4] = {h0, h1, h2, h3};
            bf16 lv[4] = {l0, l1, l2, l3};
            *(uint2*)(hi + (size_t)v * 4) = *(uint2*)hv;
            *(uint2*)(lo + (size_t)v * 4) = *(uint2*)lv;
        }
    } else {
        int total = Mr * Kp;
        for (int idx = blockIdx.x * blockDim.x + threadIdx.x; idx < total;
             idx += gridDim.x * blockDim.x) {
            int r = idx / Kp, k = idx - r * Kp;
            float v = (k < K) ? W[(size_t)r * K + k] : 0.f;
            bf16 h = __float2bfloat16(v);
            hi[idx] = h;
            lo[idx] = __float2bfloat16(v - __bfloat162float(h));
        }
    }
}

// ============================================================
// K3: bf16-split HMMA GEMM + ReLU.
//   SPLIT=true : write hi/lo bf16 for next layer.
//   SPLIT=false: fused final layer -> per-column partial W5 . relu(h4)
// ============================================================
#define OFF_AH 0
#define OFF_AL 16384
#define OFF_BH 32768
#define OFF_BL 40960
#define STAGE_BYTES 49152
#define SMEM_TOT (2*STAGE_BYTES)   // 98304

__device__ __forceinline__ void load_tile_cp(const bf16* __restrict__ G, int row0,
                                             int stride, int k0, uint32_t smd,
                                             int rows, int tid) {
    int nv = rows * 8;
    for (int v = tid; v < nv; v += 256) {
        int r = v >> 3, seg = v & 7;
        const bf16* src = G + (size_t)(row0 + r) * stride + k0 + seg * 8;
        CP16(smd + SWZ(r * 128 + seg * 16), src);
    }
}

template<bool SPLIT>
__global__ __launch_bounds__(256, 2)
void k_tgemm(const bf16* __restrict__ Ah, const bf16* __restrict__ Al,
             const bf16* __restrict__ Bh, const bf16* __restrict__ Bl,
             bf16* __restrict__ Oh, bf16* __restrict__ Ol,
             const float* __restrict__ W5, int Mdim, int K) {
    int ncols = BATCH * (1 + g_nused);
    int n0 = blockIdx.y * NTILE;
    if (n0 >= ncols) return;
    int m0 = blockIdx.x * 128;

    extern __shared__ __align__(128) char sm[];
    uint32_t smb = smem_u32(sm);
    int tid  = threadIdx.x;
    int wid  = tid >> 5, lane = tid & 31;
    int wm   = wid & 3;
    int wn   = wid >> 2;

    int a_row_l = lane & 15;
    int a_off_l = (lane >> 4) << 4;
    int b_n_l   = ((lane >> 4) << 3) + (lane & 7);
    int b_off_l = ((lane >> 3) & 1) << 4;

    float acc[2][4][4];
    #pragma unroll
    for (int i = 0; i < 2; i++)
        #pragma unroll
        for (int j = 0; j < 4; j++)
            #pragma unroll
            for (int q = 0; q < 4; q++) acc[i][j][q] = 0.f;

    int nch = K >> 6;
    {
        uint32_t sb = smb;
        load_tile_cp(Ah, m0, K, 0, sb + OFF_AH, 128, tid);
        load_tile_cp(Al, m0, K, 0, sb + OFF_AL, 128, tid);
        load_tile_cp(Bh, n0, K, 0, sb + OFF_BH, 64, tid);
        load_tile_cp(Bl, n0, K, 0, sb + OFF_BL, 64, tid);
        CP_COMMIT();
    }

    for (int c = 0; c < nch; c++) {
        if (c + 1 < nch) {
            uint32_t sb = smb + ((c + 1) & 1) * STAGE_BYTES;
            int k0 = (c + 1) << 6;
            load_tile_cp(Ah, m0, K, k0, sb + OFF_AH, 128, tid);
            load_tile_cp(Al, m0, K, k0, sb + OFF_AL, 128, tid);
            load_tile_cp(Bh, n0, K, k0, sb + OFF_BH, 64, tid);
            load_tile_cp(Bl, n0, K, k0, sb + OFF_BL, 64, tid);
            CP_COMMIT();
            CP_WAIT(1);
        } else {
            CP_WAIT(0);
        }
        __syncthreads();

        uint32_t sb = smb + (c & 1) * STAGE_BYTES;
        #pragma unroll
        for (int kk = 0; kk < 4; kk++) {
            int kb = kk << 5;
            uint32_t ah[2][4], al[2][4], bh[2][4], bl[2][4];
            #pragma unroll
            for (int ma = 0; ma < 2; ma++) {
                uint32_t off = SWZ((wm * 32 + ma * 16 + a_row_l) * 128 + kb + a_off_l);
                ldm_x4(ah[ma][0], ah[ma][1], ah[ma][2], ah[ma][3], sb + OFF_AH + off);
                ldm_x4(al[ma][0], al[ma][1], al[ma][2], al[ma][3], sb + OFF_AL + off);
            }
            #pragma unroll
            for (int nb = 0; nb < 2; nb++) {
                uint32_t off = SWZ((wn * 32 + nb * 16 + b_n_l) * 128 + kb + b_off_l);
                ldm_x4(bh[nb][0], bh[nb][1], bh[nb][2], bh[nb][3], sb + OFF_BH + off);
                ldm_x4(bl[nb][0], bl[nb][1], bl[nb][2], bl[nb][3], sb + OFF_BL + off);
            }
            #pragma unroll
            for (int ma = 0; ma < 2; ma++) {
                #pragma unroll
                for (int na = 0; na < 4; na++) {
                    const uint32_t* pbh = &bh[na >> 1][(na & 1) * 2];
                    const uint32_t* pbl = &bl[na >> 1][(na & 1) * 2];
                    mma_bf16(acc[ma][na], ah[ma], pbh);
                    mma_bf16(acc[ma][na], ah[ma], pbl);
                    mma_bf16(acc[ma][na], al[ma], pbh);
                }
            }
        }
        __syncthreads();
    }

    if (SPLIT) {
        // relu + write O[n][m] as hi/lo bf16
        #pragma unroll
        for (int ma = 0; ma < 2; ma++) {
            int mrow = m0 + wm * 32 + ma * 16 + (lane >> 2);
            #pragma unroll
            for (int na = 0; na < 4; na++) {
                int nb2 = n0 + wn * 32 + na * 8 + ((lane & 3) << 1);
                #pragma unroll
                for (int q = 0; q < 4; q++) {
                    int n = nb2 + (q & 1);
                    int m = mrow + ((q >> 1) << 3);
                    if (n < ncols) {
                        float v = fmaxf(acc[ma][na][q], 0.f);
                        bf16 h = __float2bfloat16(v);
                        Oh[(size_t)n * Mdim + m] = h;
                        Ol[(size_t)n * Mdim + m] = __float2bfloat16(v - __bfloat162float(h));
                    }
                }
            }
        }
    } else {
        // fused: per-column partial dot with W5 over this CTA's 128 m-rows
        __shared__ float sdot[NTILE];
        for (int i = tid; i < NTILE; i += 256) sdot[i] = 0.f;
        __syncthreads();
        #pragma unroll
        for (int na = 0; na < 4; na++) {
            float p0 = 0.f, p1 = 0.f;
            #pragma unroll
            for (int ma = 0; ma < 2; ma++) {
                int mb = m0 + wm * 32 + ma * 16 + (lane >> 2);
                float w5a = W5[mb], w5b = W5[mb + 8];
                p0 += fmaxf(acc[ma][na][0], 0.f) * w5a + fmaxf(acc[ma][na][2], 0.f) * w5b;
                p1 += fmaxf(acc[ma][na][1], 0.f) * w5a + fmaxf(acc[ma][na][3], 0.f) * w5b;
            }
            int ni = wn * 32 + na * 8 + ((lane & 3) << 1);
            atomicAdd(&sdot[ni], p0);
            atomicAdd(&sdot[ni + 1], p1);
        }
        __syncthreads();
        for (int i = tid; i < NTILE; i += 256) {
            int n = n0 + i;
            if (n < ncols) g_dotp[blockIdx.x * NCOLP + n] = sdot[i];
        }
    }
}

// ============================================================
// K5: sigmoid + loss (permutation-invariant; perm_idx drops out)
// ============================================================
__global__ void k_loss(const int* __restrict__ rand_idx, float* __restrict__ out) {
    int tid = threadIdx.x;
    int nloc = 1 + g_nused;
    int ncols = BATCH * nloc;
    for (int c = tid; c < ncols; c += 256) {
        float d = g_dotp[c] + g_dotp[NCOLP + c] + g_dotp[2 * NCOLP + c] + g_dotp[3 * NCOLP + c];
        g_score[c] = 1.f / (1.f + expf(-d));
    }
    __syncthreads();
    float acc = 0.f;
    for (int idx = tid; idx < BATCH * NEG_N; idx += 256) {
        int b = idx >> 7, n = idx & 127;
        int s = rand_idx[n];
        s = min(max(s, 0), NSAMP - 1);
        int u = g_slot[s];
        float v = g_score[b * nloc + u];
        acc += v * v;
    }
    if (tid < BATCH) {
        float v = g_score[tid * nloc] - 1.f;
        acc += 128.f * v * v;
    }
    __shared__ float sh[256];
    sh[tid] = acc;
    __syncthreads();
    for (int o = 128; o; o >>= 1) {
        if (tid < o) sh[tid] += sh[tid + o];
        __syncthreads();
    }
    if (tid == 0) out[0] = sh[0];
}

// ============================================================
// launch
// ============================================================
extern "C" void kernel_launch(void* const* d_in, const int* in_sizes, int n_in,
                              void* d_out, int out_size) {
    const int*   doc       = (const int*)  d_in[0];
    const float* doc_f     = (const float*)d_in[1];
    const int*   query     = (const int*)  d_in[2];
    const int*   target_s  = (const int*)  d_in[3];
    const int*   target_e  = (const int*)  d_in[4];
    const float* emb       = (const float*)d_in[7];
    const float* W1        = (const float*)d_in[8];
    const float* W2        = (const float*)d_in[9];
    const float* W3        = (const float*)d_in[10];
    const float* W4        = (const float*)d_in[11];
    const float* W5        = (const float*)d_in[12];
    const int*   rand_len  = (const int*)  d_in[13];
    const int*   rand_pos  = (const int*)  d_in[14];
    const int*   rand_idx  = (const int*)  d_in[15];
    float* out = (float*)d_out;

    bf16 *W1h,*W1l,*W2h,*W2l,*W3h,*W3l,*W4h,*W4l;
    bf16 *Fh,*Fl,*H1h,*H1l,*H2h,*H2l,*H3h,*H3l;
    cudaGetSymbolAddress((void**)&W1h, g_W1h); cudaGetSymbolAddress((void**)&W1l, g_W1l);
    cudaGetSymbolAddress((void**)&W2h, g_W2h); cudaGetSymbolAddress((void**)&W2l, g_W2l);
    cudaGetSymbolAddress((void**)&W3h, g_W3h); cudaGetSymbolAddress((void**)&W3l, g_W3l);
    cudaGetSymbolAddress((void**)&W4h, g_W4h); cudaGetSymbolAddress((void**)&W4l, g_W4l);
    cudaGetSymbolAddress((void**)&Fh,  g_Fh);  cudaGetSymbolAddress((void**)&Fl,  g_Fl);
    cudaGetSymbolAddress((void**)&H1h, g_H1h); cudaGetSymbolAddress((void**)&H1l, g_H1l);
    cudaGetSymbolAddress((void**)&H2h, g_H2h); cudaGetSymbolAddress((void**)&H2l, g_H2l);
    cudaGetSymbolAddress((void**)&H3h, g_H3h); cudaGetSymbolAddress((void**)&H3l, g_H3l);

    cudaFuncSetAttribute(k_tgemm<true>,  cudaFuncAttributeMaxDynamicSharedMemorySize, SMEM_TOT);
    cudaFuncSetAttribute(k_tgemm<false>, cudaFuncAttributeMaxDynamicSharedMemorySize, SMEM_TOT);

    k_prep<<<1, 256>>>(rand_idx);
    k_qf  <<<BATCH, 128>>>(query, emb);
    {
        dim3 gc(512, 4);
        k_conv4<<<gc, 256>>>(W1, W2, W3, W4,
                             W1h, W1l, W2h, W2l, W3h, W3l, W4h, W4l);
    }
    {
        dim3 g(NLOC, BATCH);
        k_feat<<<g, 256>>>(doc, doc_f, emb, target_s, target_e, rand_len, rand_pos);
    }
    {
        dim3 g1(HID / 128,   NTILES);
        dim3 g4(H2DIM / 128, NTILES);
        k_tgemm<true ><<<g1, 256, SMEM_TOT>>>(W1h, W1l, Fh,  Fl,  H1h, H1l, (const float*)0, HID, KP1);
        k_tgemm<true ><<<g1, 256, SMEM_TOT>>>(W2h, W2l, H1h, H1l, H2h, H2l, (const float*)0, HID, HID);
        k_tgemm<true ><<<g1, 256, SMEM_TOT>>>(W3h, W3l, H2h, H2l, H3h, H3l, (const float*)0, HID, HID);
        k_tgemm<false><<<g4, 256, SMEM_TOT>>>(W4h, W4l, H3h, H3l, (bf16*)0, (bf16*)0, W5, H2DIM, HID);
    }
    k_loss<<<1, 256>>>(rand_idx, out);
}

// round 7
// speedup vs baseline: 11.9292x; 1.7807x over previous
#include <cuda_runtime.h>
#include <cuda_fp16.h>
#include <math.h>
#include <stdint.h>

typedef __half f16;

// ----- problem constants -----
#define BATCH   32
#define LD      512
#define LQ      32
#define EDIM    300
#define NF      4
#define DDIM    304
#define MWIN    16
#define ALPHA   0.9f
#define HID     1024
#define H2DIM   512
#define CIN     1212
#define KP1     1216          // CIN padded to 64
#define PPL     9
#define NSAMP   144
#define NEG_N   128
#define NLOC    145
#define NCOL    (BATCH*NLOC)  // 4640 worst case
#define NCOLP   4704
#define NTILE   64
#define NTILES  ((NCOL + NTILE - 1) / NTILE)   // 73

// ----- scratch (device globals; no allocation allowed) -----
__device__ __align__(16) f16 g_W1[(size_t)HID*KP1];
__device__ __align__(16) f16 g_W2[(size_t)HID*HID];
__device__ __align__(16) f16 g_W3[(size_t)HID*HID];
__device__ __align__(16) f16 g_W4[(size_t)H2DIM*HID];
__device__ __align__(16) f16 g_F [(size_t)NCOLP*KP1];
__device__ __align__(16) f16 g_H1[(size_t)NCOLP*HID];
__device__ __align__(16) f16 g_H2[(size_t)NCOLP*HID];
__device__ __align__(16) f16 g_H3[(size_t)NCOLP*HID];
__device__ float g_dotp[4*NCOLP];   // per-mblock partial W5.relu(h4)
__device__ float g_score[NCOLP];
__device__ float g_qf[BATCH*EDIM];
__device__ int   g_used[NSAMP];
__device__ int   g_slot[NSAMP];
__device__ int   g_nused;

// ============================================================
// helpers
// ============================================================
__device__ __forceinline__ uint32_t smem_u32(const void* p) {
    uint32_t a;
    asm("{ .reg .u64 t; cvta.to.shared.u64 t, %1; cvt.u32.u64 %0, t; }" : "=r"(a) : "l"(p));
    return a;
}
#define SWZ(b) ((b) ^ (((b) >> 3) & 0x70))

#define CP16(dst, src) asm volatile("cp.async.ca.shared.global [%0], [%1], 16;" :: "r"(dst), "l"(src))
#define CP_COMMIT()    asm volatile("cp.async.commit_group;" ::: "memory")
#define CP_WAIT(n)     asm volatile("cp.async.wait_group %0;" :: "n"(n) : "memory")

__device__ __forceinline__ void ldm_x4(uint32_t& r0, uint32_t& r1, uint32_t& r2,
                                       uint32_t& r3, uint32_t addr) {
    asm volatile("ldmatrix.sync.aligned.m8n8.x4.shared.b16 {%0,%1,%2,%3}, [%4];"
        : "=r"(r0), "=r"(r1), "=r"(r2), "=r"(r3) : "r"(addr));
}
__device__ __forceinline__ void mma_f16(float* d, const uint32_t* a, const uint32_t* b) {
    asm volatile("mma.sync.aligned.m16n8k16.row.col.f32.f16.f16.f32 "
        "{%0,%1,%2,%3}, {%4,%5,%6,%7}, {%8,%9}, {%0,%1,%2,%3};"
        : "+f"(d[0]), "+f"(d[1]), "+f"(d[2]), "+f"(d[3])
        : "r"(a[0]), "r"(a[1]), "r"(a[2]), "r"(a[3]), "r"(b[0]), "r"(b[1]));
}

// ============================================================
// K0: dedup rand_idx -> used list + slot map (1 block)
// ============================================================
__global__ void k_prep(const int* __restrict__ rand_idx) {
    __shared__ int s_cnt[NSAMP];
    int tid = threadIdx.x;
    for (int i = tid; i < NSAMP; i += blockDim.x) s_cnt[i] = 0;
    __syncthreads();
    for (int n = tid; n < NEG_N; n += blockDim.x) {
        int s = rand_idx[n];
        s = min(max(s, 0), NSAMP - 1);
        atomicAdd(&s_cnt[s], 1);
    }
    __syncthreads();
    if (tid == 0) {
        int u = 0;
        for (int s = 0; s < NSAMP; s++) {
            if (s_cnt[s] > 0) { g_used[u] = s; g_slot[s] = u + 1; u++; }
            else              { g_slot[s] = 0; }
        }
        g_nused = u;
    }
}

// ============================================================
// K1: query FOFE vector
// ============================================================
__global__ void k_qf(const int* __restrict__ query, const float* __restrict__ emb) {
    int b = blockIdx.x;
    int tid = threadIdx.x;
    __shared__ float qw[LQ];
    __shared__ int   tok[LQ];
    if (tid < LQ) {
        float w = 1.f;
        for (int k = 0; k < LQ - 1 - tid; k++) w *= ALPHA;
        qw[tid]  = w;
        tok[tid] = query[b * LQ + tid];
    }
    __syncthreads();
    for (int e = tid; e < EDIM; e += blockDim.x) {
        float acc = 0.f;
        #pragma unroll 4
        for (int t = 0; t < LQ; t++)
            acc += qw[t] * emb[(size_t)tok[t] * EDIM + e];
        g_qf[b * EDIM + e] = acc;
    }
}

// ============================================================
// K2: build COMPACT feature matrix (fp16, K padded to KP1)
// ============================================================
__global__ void k_feat(const int* __restrict__ doc, const float* __restrict__ doc_f,
                       const float* __restrict__ emb,
                       const int* __restrict__ target_s, const int* __restrict__ target_e,
                       const int* __restrict__ rand_length, const int* __restrict__ rand_position) {
    int local = blockIdx.x;
    int b     = blockIdx.y;
    int nloc  = 1 + g_nused;
    if (local >= nloc) return;

    __shared__ int   stok[3][16];
    __shared__ int   spos[3][16];
    __shared__ float sw[3][16];
    __shared__ float sdf[3][4];

    int tid = threadIdx.x;

    int base_l, pos_a, ka, base_r;
    if (local == 0) {
        int ts = target_s[b], te = target_e[b];
        base_l = max(ts - 1, 0);
        pos_a  = min(max(te, 0), LD - 1);
        ka     = te - ts;
        base_r = min(te + 1, LD - 1);
    } else {
        int s  = g_used[local - 1];
        int i  = s / PPL, j = s % PPL;
        int rl = min(max(rand_length[i], 0), MWIN - 1);
        int p  = rand_position[i * PPL + j];
        p      = min(max(p, 0), LD - 1);
        pos_a  = p;
        ka     = rl;
        base_l = min(max(p - 1, 0), LD - 1);
        base_r = min(max(p + rl + 1, 0), LD - 1);
    }

    if (tid < 48) {
        int seg = tid >> 4, k = tid & 15;
        float w = 1.f;
        for (int i = 0; i < k; i++) w *= ALPHA;
        int t; bool valid;
        if (seg == 0)      { t = base_l - k; valid = (t >= 0); }
        else if (seg == 1) { t = pos_a - k; valid = (t >= 0) && (k <= ka); }
        else               { t = base_r + k; valid = (t < LD); }
        int tc = min(max(t, 0), LD - 1);
        sw[seg][k]   = valid ? w : 0.f;
        stok[seg][k] = valid ? doc[b * LD + tc] : 0;
        spos[seg][k] = tc;
    }
    __syncthreads();
    if (tid < 12) {
        int seg = tid >> 2, f = tid & 3;
        float acc = 0.f;
        #pragma unroll
        for (int k = 0; k < 16; k++)
            acc += sw[seg][k] * doc_f[((size_t)(b * LD + spos[seg][k])) * NF + f];
        sdf[seg][f] = acc;
    }
    __syncthreads();

    size_t row = (size_t)(b * nloc + local) * KP1;
    for (int c = tid; c < KP1; c += blockDim.x) {
        float acc = 0.f;
        if (c < 3 * DDIM) {
            int seg = (c >= 2 * DDIM) ? 2 : ((c >= DDIM) ? 1 : 0);
            int ch = c - seg * DDIM;
            if (ch < EDIM) {
                #pragma unroll
                for (int k = 0; k < 16; k++)
                    acc += sw[seg][k] * emb[(size_t)stok[seg][k] * EDIM + ch];
            } else {
                acc = sdf[seg][ch - EDIM];
            }
        } else if (c < CIN) {
            acc = g_qf[b * EDIM + (c - 3 * DDIM)];
        }
        g_F[row + c] = __float2half(acc);
    }
}

// ============================================================
// K2b: all-weights -> fp16 (single launch; gridDim.y = weight id)
// ============================================================
__global__ void k_conv4(const float* __restrict__ Wa, const float* __restrict__ Wb,
                        const float* __restrict__ Wc, const float* __restrict__ Wd,
                        f16* __restrict__ oa, f16* __restrict__ ob,
                        f16* __restrict__ oc, f16* __restrict__ od) {
    int which = blockIdx.y;
    const float* W; f16* o; int Mr, K, Kp;
    if      (which == 0) { W = Wa; o = oa; Mr = HID;   K = CIN; Kp = KP1; }
    else if (which == 1) { W = Wb; o = ob; Mr = HID;   K = HID; Kp = HID; }
    else if (which == 2) { W = Wc; o = oc; Mr = HID;   K = HID; Kp = HID; }
    else                 { W = Wd; o = od; Mr = H2DIM; K = HID; Kp = HID; }

    if (K == Kp) {
        int total4 = (Mr * Kp) >> 2;
        for (int v = blockIdx.x * blockDim.x + threadIdx.x; v < total4;
             v += gridDim.x * blockDim.x) {
            float4 f = *(const float4*)(W + (size_t)v * 4);
            f16 hv[4] = {__float2half(f.x), __float2half(f.y),
                         __float2half(f.z), __float2half(f.w)};
            *(uint2*)(o + (size_t)v * 4) = *(uint2*)hv;
        }
    } else {
        int total = Mr * Kp;
        for (int idx = blockIdx.x * blockDim.x + threadIdx.x; idx < total;
             idx += gridDim.x * blockDim.x) {
            int r = idx / Kp, k = idx - r * Kp;
            float v = (k < K) ? W[(size_t)r * K + k] : 0.f;
            o[idx] = __float2half(v);
        }
    }
}

// ============================================================
// K3: fp16 HMMA GEMM + ReLU (single MMA per fragment pair).
//   SPLIT=true : write fp16 for next layer.
//   SPLIT=false: fused final layer -> per-column partial W5 . relu(h4)
//   CTA tile 128x64, 8 warps (4M x 2N), warp tile 32x32.
//   K chunks of 64, 3-stage cp.async pipeline, SW128 swizzle + ldmatrix.
// ============================================================
#define OFF_A 0
#define OFF_B 16384
#define STAGE_BYTES 24576
#define NSTAGE 3
#define SMEM_TOT (NSTAGE*STAGE_BYTES)   // 73728

__device__ __forceinline__ void load_tile_cp(const f16* __restrict__ G, int row0,
                                             int stride, int k0, uint32_t smd,
                                             int rows, int tid) {
    int nv = rows * 8;
    for (int v = tid; v < nv; v += 256) {
        int r = v >> 3, seg = v & 7;
        const f16* src = G + (size_t)(row0 + r) * stride + k0 + seg * 8;
        CP16(smd + SWZ(r * 128 + seg * 16), src);
    }
}

template<bool SPLIT>
__global__ __launch_bounds__(256, 2)
void k_tgemm(const f16* __restrict__ A, const f16* __restrict__ B,
             f16* __restrict__ O, const float* __restrict__ W5, int Mdim, int K) {
    int ncols = BATCH * (1 + g_nused);
    int n0 = blockIdx.y * NTILE;
    if (n0 >= ncols) return;
    int m0 = blockIdx.x * 128;

    extern __shared__ __align__(128) char sm[];
    uint32_t smb = smem_u32(sm);
    int tid  = threadIdx.x;
    int wid  = tid >> 5, lane = tid & 31;
    int wm   = wid & 3;
    int wn   = wid >> 2;

    int a_row_l = lane & 15;
    int a_off_l = (lane >> 4) << 4;
    int b_n_l   = ((lane >> 4) << 3) + (lane & 7);
    int b_off_l = ((lane >> 3) & 1) << 4;

    float acc[2][4][4];
    #pragma unroll
    for (int i = 0; i < 2; i++)
        #pragma unroll
        for (int j = 0; j < 4; j++)
            #pragma unroll
            for (int q = 0; q < 4; q++) acc[i][j][q] = 0.f;

    int nch = K >> 6;
    // prefetch chunks 0,1
    #pragma unroll
    for (int p = 0; p < 2; p++) {
        if (p < nch) {
            uint32_t sb = smb + p * STAGE_BYTES;
            load_tile_cp(A, m0, K, p << 6, sb + OFF_A, 128, tid);
            load_tile_cp(B, n0, K, p << 6, sb + OFF_B, 64, tid);
            CP_COMMIT();
        }
    }

    for (int c = 0; c < nch; c++) {
        if (c + 2 < nch) {
            uint32_t sb = smb + ((c + 2) % NSTAGE) * STAGE_BYTES;
            int k0 = (c + 2) << 6;
            load_tile_cp(A, m0, K, k0, sb + OFF_A, 128, tid);
            load_tile_cp(B, n0, K, k0, sb + OFF_B, 64, tid);
            CP_COMMIT();
            CP_WAIT(2);
        } else if (c + 1 < nch) {
            CP_WAIT(1);
        } else {
            CP_WAIT(0);
        }
        __syncthreads();

        uint32_t sb = smb + (c % NSTAGE) * STAGE_BYTES;
        #pragma unroll
        for (int kk = 0; kk < 4; kk++) {
            int kb = kk << 5;
            uint32_t af[2][4], bf[2][4];
            #pragma unroll
            for (int ma = 0; ma < 2; ma++) {
                uint32_t off = SWZ((wm * 32 + ma * 16 + a_row_l) * 128 + kb + a_off_l);
                ldm_x4(af[ma][0], af[ma][1], af[ma][2], af[ma][3], sb + OFF_A + off);
            }
            #pragma unroll
            for (int nb = 0; nb < 2; nb++) {
                uint32_t off = SWZ((wn * 32 + nb * 16 + b_n_l) * 128 + kb + b_off_l);
                ldm_x4(bf[nb][0], bf[nb][1], bf[nb][2], bf[nb][3], sb + OFF_B + off);
            }
            #pragma unroll
            for (int ma = 0; ma < 2; ma++) {
                #pragma unroll
                for (int na = 0; na < 4; na++) {
                    mma_f16(acc[ma][na], af[ma], &bf[na >> 1][(na & 1) * 2]);
                }
            }
        }
        __syncthreads();
    }

    if (SPLIT) {
        #pragma unroll
        for (int ma = 0; ma < 2; ma++) {
            int mrow = m0 + wm * 32 + ma * 16 + (lane >> 2);
            #pragma unroll
            for (int na = 0; na < 4; na++) {
                int nb2 = n0 + wn * 32 + na * 8 + ((lane & 3) << 1);
                #pragma unroll
                for (int q = 0; q < 4; q++) {
                    int n = nb2 + (q & 1);
                    int m = mrow + ((q >> 1) << 3);
                    if (n < ncols)
                        O[(size_t)n * Mdim + m] = __float2half(fmaxf(acc[ma][na][q], 0.f));
                }
            }
        }
    } else {
        __shared__ float sdot[NTILE];
        for (int i = tid; i < NTILE; i += 256) sdot[i] = 0.f;
        __syncthreads();
        #pragma unroll
        for (int na = 0; na < 4; na++) {
            float p0 = 0.f, p1 = 0.f;
            #pragma unroll
            for (int ma = 0; ma < 2; ma++) {
                int mb = m0 + wm * 32 + ma * 16 + (lane >> 2);
                float w5a = W5[mb], w5b = W5[mb + 8];
                p0 += fmaxf(acc[ma][na][0], 0.f) * w5a + fmaxf(acc[ma][na][2], 0.f) * w5b;
                p1 += fmaxf(acc[ma][na][1], 0.f) * w5a + fmaxf(acc[ma][na][3], 0.f) * w5b;
            }
            int ni = wn * 32 + na * 8 + ((lane & 3) << 1);
            atomicAdd(&sdot[ni], p0);
            atomicAdd(&sdot[ni + 1], p1);
        }
        __syncthreads();
        for (int i = tid; i < NTILE; i += 256) {
            int n = n0 + i;
            if (n < ncols) g_dotp[blockIdx.x * NCOLP + n] = sdot[i];
        }
    }
}

// ============================================================
// K5: sigmoid + loss (permutation-invariant; perm_idx drops out)
// ============================================================
__global__ void k_loss(const int* __restrict__ rand_idx, float* __restrict__ out) {
    int tid = threadIdx.x;
    int nloc = 1 + g_nused;
    int ncols = BATCH * nloc;
    for (int c = tid; c < ncols; c += 256) {
        float d = g_dotp[c] + g_dotp[NCOLP + c] + g_dotp[2 * NCOLP + c] + g_dotp[3 * NCOLP + c];
        g_score[c] = 1.f / (1.f + expf(-d));
    }
    __syncthreads();
    float acc = 0.f;
    for (int idx = tid; idx < BATCH * NEG_N; idx += 256) {
        int b = idx >> 7, n = idx & 127;
        int s = rand_idx[n];
        s = min(max(s, 0), NSAMP - 1);
        int u = g_slot[s];
        float v = g_score[b * nloc + u];
        acc += v * v;
    }
    if (tid < BATCH) {
        float v = g_score[tid * nloc] - 1.f;
        acc += 128.f * v * v;
    }
    __shared__ float sh[256];
    sh[tid] = acc;
    __syncthreads();
    for (int o = 128; o; o >>= 1) {
        if (tid < o) sh[tid] += sh[tid + o];
        __syncthreads();
    }
    if (tid == 0) out[0] = sh[0];
}

// ============================================================
// launch
// ============================================================
extern "C" void kernel_launch(void* const* d_in, const int* in_sizes, int n_in,
                              void* d_out, int out_size) {
    const int*   doc       = (const int*)  d_in[0];
    const float* doc_f     = (const float*)d_in[1];
    const int*   query     = (const int*)  d_in[2];
    const int*   target_s  = (const int*)  d_in[3];
    const int*   target_e  = (const int*)  d_in[4];
    const float* emb       = (const float*)d_in[7];
    const float* W1        = (const float*)d_in[8];
    const float* W2        = (const float*)d_in[9];
    const float* W3        = (const float*)d_in[10];
    const float* W4        = (const float*)d_in[11];
    const float* W5        = (const float*)d_in[12];
    const int*   rand_len  = (const int*)  d_in[13];
    const int*   rand_pos  = (const int*)  d_in[14];
    const int*   rand_idx  = (const int*)  d_in[15];
    float* out = (float*)d_out;

    f16 *W1p,*W2p,*W3p,*W4p,*F,*H1,*H2,*H3;
    cudaGetSymbolAddress((void**)&W1p, g_W1);
    cudaGetSymbolAddress((void**)&W2p, g_W2);
    cudaGetSymbolAddress((void**)&W3p, g_W3);
    cudaGetSymbolAddress((void**)&W4p, g_W4);
    cudaGetSymbolAddress((void**)&F,   g_F);
    cudaGetSymbolAddress((void**)&H1,  g_H1);
    cudaGetSymbolAddress((void**)&H2,  g_H2);
    cudaGetSymbolAddress((void**)&H3,  g_H3);

    cudaFuncSetAttribute(k_tgemm<true>,  cudaFuncAttributeMaxDynamicSharedMemorySize, SMEM_TOT);
    cudaFuncSetAttribute(k_tgemm<false>, cudaFuncAttributeMaxDynamicSharedMemorySize, SMEM_TOT);

    k_prep<<<1, 256>>>(rand_idx);
    k_qf  <<<BATCH, 128>>>(query, emb);
    {
        dim3 gc(512, 4);
        k_conv4<<<gc, 256>>>(W1, W2, W3, W4, W1p, W2p, W3p, W4p);
    }
    {
        dim3 g(NLOC, BATCH);
        k_feat<<<g, 256>>>(doc, doc_f, emb, target_s, target_e, rand_len, rand_pos);
    }
    {
        dim3 g1(HID / 128,   NTILES);
        dim3 g4(H2DIM / 128, NTILES);
        k_tgemm<true ><<<g1, 256, SMEM_TOT>>>(W1p, F,  H1, (const float*)0, HID, KP1);
        k_tgemm<true ><<<g1, 256, SMEM_TOT>>>(W2p, H1, H2, (const float*)0, HID, HID);
        k_tgemm<true ><<<g1, 256, SMEM_TOT>>>(W3p, H2, H3, (const float*)0, HID, HID);
        k_tgemm<false><<<g4, 256, SMEM_TOT>>>(W4p, H3, (f16*)0, W5, H2DIM, HID);
    }
    k_loss<<<1, 256>>>(rand_idx, out);
}

// round 8
// speedup vs baseline: 15.9630x; 1.3381x over previous
#include <cuda_runtime.h>
#include <cuda_fp16.h>
#include <math.h>
#include <stdint.h>

typedef __half f16;

// ----- problem constants -----
#define BATCH   32
#define LD      512
#define LQ      32
#define EDIM    300
#define NF      4
#define DDIM    304
#define MWIN    16
#define ALPHA   0.9f
#define HID     1024
#define H2DIM   512
#define CIN     1212
#define KP1     1216          // CIN padded to 64
#define PPL     9
#define NSAMP   144
#define NEG_N   128
#define NLOC    145
#define NCOL    (BATCH*NLOC)  // 4640 worst case
#define NCOLP   4704
#define NTILE   64
#define NTILES  ((NCOL + NTILE - 1) / NTILE)   // 73
#define MB4     (H2DIM/64)    // 8 m-blocks in layer 4

// ----- scratch (device globals; no allocation allowed) -----
__device__ __align__(16) f16 g_W1[(size_t)HID*KP1];
__device__ __align__(16) f16 g_W2[(size_t)HID*HID];
__device__ __align__(16) f16 g_W3[(size_t)HID*HID];
__device__ __align__(16) f16 g_W4[(size_t)H2DIM*HID];
__device__ __align__(16) f16 g_F [(size_t)NCOLP*KP1];
__device__ __align__(16) f16 g_H1[(size_t)NCOLP*HID];
__device__ __align__(16) f16 g_H2[(size_t)NCOLP*HID];
__device__ __align__(16) f16 g_H3[(size_t)NCOLP*HID];
__device__ float g_dotp[MB4*NCOLP];   // per-mblock partial W5.relu(h4)
__device__ float g_score[NCOLP];
__device__ float g_qf[BATCH*EDIM];
__device__ int   g_used[NSAMP];
__device__ int   g_slot[NSAMP];
__device__ int   g_nused;

// ============================================================
// helpers
// ============================================================
__device__ __forceinline__ uint32_t smem_u32(const void* p) {
    uint32_t a;
    asm("{ .reg .u64 t; cvta.to.shared.u64 t, %1; cvt.u32.u64 %0, t; }" : "=r"(a) : "l"(p));
    return a;
}
#define SWZ(b) ((b) ^ (((b) >> 3) & 0x70))

#define CP16(dst, src) asm volatile("cp.async.ca.shared.global [%0], [%1], 16;" :: "r"(dst), "l"(src))
#define CP_COMMIT()    asm volatile("cp.async.commit_group;" ::: "memory")
#define CP_WAIT(n)     asm volatile("cp.async.wait_group %0;" :: "n"(n) : "memory")

__device__ __forceinline__ void ldm_x4(uint32_t& r0, uint32_t& r1, uint32_t& r2,
                                       uint32_t& r3, uint32_t addr) {
    asm volatile("ldmatrix.sync.aligned.m8n8.x4.shared.b16 {%0,%1,%2,%3}, [%4];"
        : "=r"(r0), "=r"(r1), "=r"(r2), "=r"(r3) : "r"(addr));
}
__device__ __forceinline__ void mma_f16(float* d, const uint32_t* a, const uint32_t* b) {
    asm volatile("mma.sync.aligned.m16n8k16.row.col.f32.f16.f16.f32 "
        "{%0,%1,%2,%3}, {%4,%5,%6,%7}, {%8,%9}, {%0,%1,%2,%3};"
        : "+f"(d[0]), "+f"(d[1]), "+f"(d[2]), "+f"(d[3])
        : "r"(a[0]), "r"(a[1]), "r"(a[2]), "r"(a[3]), "r"(b[0]), "r"(b[1]));
}

// ============================================================
// K0: block 0: dedup rand_idx; blocks 1..32: query FOFE vector
// ============================================================
__global__ void k_prep_qf(const int* __restrict__ rand_idx,
                          const int* __restrict__ query, const float* __restrict__ emb) {
    int tid = threadIdx.x;
    if (blockIdx.x == 0) {
        __shared__ int s_cnt[NSAMP];
        for (int i = tid; i < NSAMP; i += blockDim.x) s_cnt[i] = 0;
        __syncthreads();
        for (int n = tid; n < NEG_N; n += blockDim.x) {
            int s = rand_idx[n];
            s = min(max(s, 0), NSAMP - 1);
            atomicAdd(&s_cnt[s], 1);
        }
        __syncthreads();
        if (tid == 0) {
            int u = 0;
            for (int s = 0; s < NSAMP; s++) {
                if (s_cnt[s] > 0) { g_used[u] = s; g_slot[s] = u + 1; u++; }
                else              { g_slot[s] = 0; }
            }
            g_nused = u;
        }
    } else {
        int b = blockIdx.x - 1;
        __shared__ float qw[LQ];
        __shared__ int   tok[LQ];
        if (tid < LQ) {
            float w = 1.f;
            for (int k = 0; k < LQ - 1 - tid; k++) w *= ALPHA;
            qw[tid]  = w;
            tok[tid] = query[b * LQ + tid];
        }
        __syncthreads();
        for (int e = tid; e < EDIM; e += blockDim.x) {
            float acc = 0.f;
            #pragma unroll 4
            for (int t = 0; t < LQ; t++)
                acc += qw[t] * emb[(size_t)tok[t] * EDIM + e];
            g_qf[b * EDIM + e] = acc;
        }
    }
}

// ============================================================
// K2: build COMPACT feature matrix (fp16, K padded to KP1)
// ============================================================
__global__ void k_feat(const int* __restrict__ doc, const float* __restrict__ doc_f,
                       const float* __restrict__ emb,
                       const int* __restrict__ target_s, const int* __restrict__ target_e,
                       const int* __restrict__ rand_length, const int* __restrict__ rand_position) {
    int local = blockIdx.x;
    int b     = blockIdx.y;
    int nloc  = 1 + g_nused;
    if (local >= nloc) return;

    __shared__ int   stok[3][16];
    __shared__ int   spos[3][16];
    __shared__ float sw[3][16];
    __shared__ float sdf[3][4];

    int tid = threadIdx.x;

    int base_l, pos_a, ka, base_r;
    if (local == 0) {
        int ts = target_s[b], te = target_e[b];
        base_l = max(ts - 1, 0);
        pos_a  = min(max(te, 0), LD - 1);
        ka     = te - ts;
        base_r = min(te + 1, LD - 1);
    } else {
        int s  = g_used[local - 1];
        int i  = s / PPL, j = s % PPL;
        int rl = min(max(rand_length[i], 0), MWIN - 1);
        int p  = rand_position[i * PPL + j];
        p      = min(max(p, 0), LD - 1);
        pos_a  = p;
        ka     = rl;
        base_l = min(max(p - 1, 0), LD - 1);
        base_r = min(max(p + rl + 1, 0), LD - 1);
    }

    if (tid < 48) {
        int seg = tid >> 4, k = tid & 15;
        float w = 1.f;
        for (int i = 0; i < k; i++) w *= ALPHA;
        int t; bool valid;
        if (seg == 0)      { t = base_l - k; valid = (t >= 0); }
        else if (seg == 1) { t = pos_a - k; valid = (t >= 0) && (k <= ka); }
        else               { t = base_r + k; valid = (t < LD); }
        int tc = min(max(t, 0), LD - 1);
        sw[seg][k]   = valid ? w : 0.f;
        stok[seg][k] = valid ? doc[b * LD + tc] : 0;
        spos[seg][k] = tc;
    }
    __syncthreads();
    if (tid < 12) {
        int seg = tid >> 2, f = tid & 3;
        float acc = 0.f;
        #pragma unroll
        for (int k = 0; k < 16; k++)
            acc += sw[seg][k] * doc_f[((size_t)(b * LD + spos[seg][k])) * NF + f];
        sdf[seg][f] = acc;
    }
    __syncthreads();

    size_t row = (size_t)(b * nloc + local) * KP1;
    for (int c = tid; c < KP1; c += blockDim.x) {
        float acc = 0.f;
        if (c < 3 * DDIM) {
            int seg = (c >= 2 * DDIM) ? 2 : ((c >= DDIM) ? 1 : 0);
            int ch = c - seg * DDIM;
            if (ch < EDIM) {
                #pragma unroll
                for (int k = 0; k < 16; k++)
                    acc += sw[seg][k] * emb[(size_t)stok[seg][k] * EDIM + ch];
            } else {
                acc = sdf[seg][ch - EDIM];
            }
        } else if (c < CIN) {
            acc = g_qf[b * EDIM + (c - 3 * DDIM)];
        }
        g_F[row + c] = __float2half(acc);
    }
}

// ============================================================
// K2b: all-weights -> fp16 (single launch; gridDim.y = weight id)
// ============================================================
__global__ void k_conv4(const float* __restrict__ Wa, const float* __restrict__ Wb,
                        const float* __restrict__ Wc, const float* __restrict__ Wd,
                        f16* __restrict__ oa, f16* __restrict__ ob,
                        f16* __restrict__ oc, f16* __restrict__ od) {
    int which = blockIdx.y;
    const float* W; f16* o; int Mr, K, Kp;
    if      (which == 0) { W = Wa; o = oa; Mr = HID;   K = CIN; Kp = KP1; }
    else if (which == 1) { W = Wb; o = ob; Mr = HID;   K = HID; Kp = HID; }
    else if (which == 2) { W = Wc; o = oc; Mr = HID;   K = HID; Kp = HID; }
    else                 { W = Wd; o = od; Mr = H2DIM; K = HID; Kp = HID; }

    if (K == Kp) {
        int total4 = (Mr * Kp) >> 2;
        for (int v = blockIdx.x * blockDim.x + threadIdx.x; v < total4;
             v += gridDim.x * blockDim.x) {
            float4 f = *(const float4*)(W + (size_t)v * 4);
            f16 hv[4] = {__float2half(f.x), __float2half(f.y),
                         __float2half(f.z), __float2half(f.w)};
            *(uint2*)(o + (size_t)v * 4) = *(uint2*)hv;
        }
    } else {
        int total = Mr * Kp;
        for (int idx = blockIdx.x * blockDim.x + threadIdx.x; idx < total;
             idx += gridDim.x * blockDim.x) {
            int r = idx / Kp, k = idx - r * Kp;
            float v = (k < K) ? W[(size_t)r * K + k] : 0.f;
            o[idx] = __float2half(v);
        }
    }
}

// ============================================================
// K3: fp16 HMMA GEMM + ReLU.
//   CTA tile 64x64, 4 warps (2M x 2N), warp tile 32x32.
//   K chunks of 64, 3-stage cp.async pipeline, SW128 swizzle + ldmatrix.
//   16KB/stage -> 48KB/CTA -> up to 4 CTAs/SM; active grid ~272 (~2/SM).
// ============================================================
#define OFF_A 0
#define OFF_B 8192
#define STAGE_BYTES 16384
#define NSTAGE 3
#define SMEM_TOT (NSTAGE*STAGE_BYTES)   // 49152

__device__ __forceinline__ void load_tile_cp(const f16* __restrict__ G, int row0,
                                             int stride, int k0, uint32_t smd, int tid) {
    // 64 rows x 64 f16 = 64 x 8 vec16 = 512 vectors, 128 threads -> 4 each
    #pragma unroll
    for (int it = 0; it < 4; it++) {
        int v = tid + it * 128;
        int r = v >> 3, seg = v & 7;
        const f16* src = G + (size_t)(row0 + r) * stride + k0 + seg * 8;
        CP16(smd + SWZ(r * 128 + seg * 16), src);
    }
}

template<bool SPLIT>
__global__ __launch_bounds__(128, 4)
void k_tgemm(const f16* __restrict__ A, const f16* __restrict__ B,
             f16* __restrict__ O, const float* __restrict__ W5, int Mdim, int K) {
    int ncols = BATCH * (1 + g_nused);
    int n0 = blockIdx.y * NTILE;
    if (n0 >= ncols) return;
    int m0 = blockIdx.x * 64;

    extern __shared__ __align__(128) char sm[];
    uint32_t smb = smem_u32(sm);
    int tid  = threadIdx.x;
    int wid  = tid >> 5, lane = tid & 31;
    int wm   = wid & 1;          // 2 warps over M (32 rows each)
    int wn   = wid >> 1;         // 2 warps over N (32 cols each)

    int a_row_l = lane & 15;
    int a_off_l = (lane >> 4) << 4;
    int b_n_l   = ((lane >> 4) << 3) + (lane & 7);
    int b_off_l = ((lane >> 3) & 1) << 4;

    float acc[2][4][4];
    #pragma unroll
    for (int i = 0; i < 2; i++)
        #pragma unroll
        for (int j = 0; j < 4; j++)
            #pragma unroll
            for (int q = 0; q < 4; q++) acc[i][j][q] = 0.f;

    int nch = K >> 6;
    #pragma unroll
    for (int p = 0; p < 2; p++) {
        if (p < nch) {
            uint32_t sb = smb + p * STAGE_BYTES;
            load_tile_cp(A, m0, K, p << 6, sb + OFF_A, tid);
            load_tile_cp(B, n0, K, p << 6, sb + OFF_B, tid);
            CP_COMMIT();
        }
    }

    for (int c = 0; c < nch; c++) {
        if (c + 2 < nch) {
            uint32_t sb = smb + ((c + 2) % NSTAGE) * STAGE_BYTES;
            int k0 = (c + 2) << 6;
            load_tile_cp(A, m0, K, k0, sb + OFF_A, tid);
            load_tile_cp(B, n0, K, k0, sb + OFF_B, tid);
            CP_COMMIT();
            CP_WAIT(2);
        } else if (c + 1 < nch) {
            CP_WAIT(1);
        } else {
            CP_WAIT(0);
        }
        __syncthreads();

        uint32_t sb = smb + (c % NSTAGE) * STAGE_BYTES;
        #pragma unroll
        for (int kk = 0; kk < 4; kk++) {
            int kb = kk << 5;
            uint32_t af[2][4], bf[2][4];
            #pragma unroll
            for (int ma = 0; ma < 2; ma++) {
                uint32_t off = SWZ((wm * 32 + ma * 16 + a_row_l) * 128 + kb + a_off_l);
                ldm_x4(af[ma][0], af[ma][1], af[ma][2], af[ma][3], sb + OFF_A + off);
            }
            #pragma unroll
            for (int nb = 0; nb < 2; nb++) {
                uint32_t off = SWZ((wn * 32 + nb * 16 + b_n_l) * 128 + kb + b_off_l);
                ldm_x4(bf[nb][0], bf[nb][1], bf[nb][2], bf[nb][3], sb + OFF_B + off);
            }
            #pragma unroll
            for (int ma = 0; ma < 2; ma++) {
                #pragma unroll
                for (int na = 0; na < 4; na++) {
                    mma_f16(acc[ma][na], af[ma], &bf[na >> 1][(na & 1) * 2]);
                }
            }
        }
        __syncthreads();
    }

    if (SPLIT) {
        #pragma unroll
        for (int ma = 0; ma < 2; ma++) {
            int mrow = m0 + wm * 32 + ma * 16 + (lane >> 2);
            #pragma unroll
            for (int na = 0; na < 4; na++) {
                int nb2 = n0 + wn * 32 + na * 8 + ((lane & 3) << 1);
                #pragma unroll
                for (int q = 0; q < 4; q++) {
                    int n = nb2 + (q & 1);
                    int m = mrow + ((q >> 1) << 3);
                    if (n < ncols)
                        O[(size_t)n * Mdim + m] = __float2half(fmaxf(acc[ma][na][q], 0.f));
                }
            }
        }
    } else {
        __shared__ float sdot[NTILE];
        for (int i = tid; i < NTILE; i += 128) sdot[i] = 0.f;
        __syncthreads();
        #pragma unroll
        for (int na = 0; na < 4; na++) {
            float p0 = 0.f, p1 = 0.f;
            #pragma unroll
            for (int ma = 0; ma < 2; ma++) {
                int mb = m0 + wm * 32 + ma * 16 + (lane >> 2);
                float w5a = W5[mb], w5b = W5[mb + 8];
                p0 += fmaxf(acc[ma][na][0], 0.f) * w5a + fmaxf(acc[ma][na][2], 0.f) * w5b;
                p1 += fmaxf(acc[ma][na][1], 0.f) * w5a + fmaxf(acc[ma][na][3], 0.f) * w5b;
            }
            int ni = wn * 32 + na * 8 + ((lane & 3) << 1);
            atomicAdd(&sdot[ni], p0);
            atomicAdd(&sdot[ni + 1], p1);
        }
        __syncthreads();
        for (int i = tid; i < NTILE; i += 128) {
            int n = n0 + i;
            if (n < ncols) g_dotp[blockIdx.x * NCOLP + n] = sdot[i];
        }
    }
}

// ============================================================
// K5: sigmoid + loss (permutation-invariant; perm_idx drops out)
// ============================================================
__global__ void k_loss(const int* __restrict__ rand_idx, float* __restrict__ out) {
    int tid = threadIdx.x;
    int nloc = 1 + g_nused;
    int ncols = BATCH * nloc;
    for (int c = tid; c < ncols; c += 256) {
        float d = 0.f;
        #pragma unroll
        for (int p = 0; p < MB4; p++) d += g_dotp[p * NCOLP + c];
        g_score[c] = 1.f / (1.f + expf(-d));
    }
    __syncthreads();
    float acc = 0.f;
    for (int idx = tid; idx < BATCH * NEG_N; idx += 256) {
        int b = idx >> 7, n = idx & 127;
        int s = rand_idx[n];
        s = min(max(s, 0), NSAMP - 1);
        int u = g_slot[s];
        float v = g_score[b * nloc + u];
        acc += v * v;
    }
    if (tid < BATCH) {
        float v = g_score[tid * nloc] - 1.f;
        acc += 128.f * v * v;
    }
    __shared__ float sh[256];
    sh[tid] = acc;
    __syncthreads();
    for (int o = 128; o; o >>= 1) {
        if (tid < o) sh[tid] += sh[tid + o];
        __syncthreads();
    }
    if (tid == 0) out[0] = sh[0];
}

// ============================================================
// launch
// ============================================================
extern "C" void kernel_launch(void* const* d_in, const int* in_sizes, int n_in,
                              void* d_out, int out_size) {
    const int*   doc       = (const int*)  d_in[0];
    const float* doc_f     = (const float*)d_in[1];
    const int*   query     = (const int*)  d_in[2];
    const int*   target_s  = (const int*)  d_in[3];
    const int*   target_e  = (const int*)  d_in[4];
    const float* emb       = (const float*)d_in[7];
    const float* W1        = (const float*)d_in[8];
    const float* W2        = (const float*)d_in[9];
    const float* W3        = (const float*)d_in[10];
    const float* W4        = (const float*)d_in[11];
    const float* W5        = (const float*)d_in[12];
    const int*   rand_len  = (const int*)  d_in[13];
    const int*   rand_pos  = (const int*)  d_in[14];
    const int*   rand_idx  = (const int*)  d_in[15];
    float* out = (float*)d_out;

    f16 *W1p,*W2p,*W3p,*W4p,*F,*H1,*H2,*H3;
    cudaGetSymbolAddress((void**)&W1p, g_W1);
    cudaGetSymbolAddress((void**)&W2p, g_W2);
    cudaGetSymbolAddress((void**)&W3p, g_W3);
    cudaGetSymbolAddress((void**)&W4p, g_W4);
    cudaGetSymbolAddress((void**)&F,   g_F);
    cudaGetSymbolAddress((void**)&H1,  g_H1);
    cudaGetSymbolAddress((void**)&H2,  g_H2);
    cudaGetSymbolAddress((void**)&H3,  g_H3);

    cudaFuncSetAttribute(k_tgemm<true>,  cudaFuncAttributeMaxDynamicSharedMemorySize, SMEM_TOT);
    cudaFuncSetAttribute(k_tgemm<false>, cudaFuncAttributeMaxDynamicSharedMemorySize, SMEM_TOT);

    k_prep_qf<<<1 + BATCH, 256>>>(rand_idx, query, emb);
    {
        dim3 gc(512, 4);
        k_conv4<<<gc, 256>>>(W1, W2, W3, W4, W1p, W2p, W3p, W4p);
    }
    {
        dim3 g(NLOC, BATCH);
        k_feat<<<g, 256>>>(doc, doc_f, emb, target_s, target_e, rand_len, rand_pos);
    }
    {
        dim3 g1(HID / 64,   NTILES);
        dim3 g4(H2DIM / 64, NTILES);
        k_tgemm<true ><<<g1, 128, SMEM_TOT>>>(W1p, F,  H1, (const float*)0, HID, KP1);
        k_tgemm<true ><<<g1, 128, SMEM_TOT>>>(W2p, H1, H2, (const float*)0, HID, HID);
        k_tgemm<true ><<<g1, 128, SMEM_TOT>>>(W3p, H2, H3, (const float*)0, HID, HID);
        k_tgemm<false><<<g4, 128, SMEM_TOT>>>(W4p, H3, (f16*)0, W5, H2DIM, HID);
    }
    k_loss<<<1, 256>>>(rand_idx, out);
}